// round 1
// baseline (speedup 1.0000x reference)
#include <cuda_runtime.h>

constexpr int CB  = 2;
constexpr int CS  = 2048;
constexpr int CD  = 1024;
constexpr int CH  = 16;
constexpr int CDK = 64;
constexpr int CDFF= 4096;
constexpr int CM  = CB * CS;   // 4096

// ------------------------- scratch (device globals; no cudaMalloc allowed) ----
__device__ float g_q  [(size_t)CB*CH*CS*CDK];
__device__ float g_k  [(size_t)CB*CH*CS*CDK];
__device__ float g_v  [(size_t)CB*CH*CS*CDK];
__device__ float g_E  [(size_t)CB*CH*CS*CS];     // exp(scores/8), 537 MB
__device__ float g_rd [(size_t)CB*CS*CS];        // 1 / sum_h exp
__device__ float g_ctx[(size_t)CM*CD];           // context in [b,s,h,dk] layout
__device__ float g_t0 [(size_t)CM*CD];           // attn_out, then ffn2 out
__device__ float g_x1 [(size_t)CM*CD];
__device__ float g_ff [(size_t)CM*CDFF];

// ------------------------- FMA-only exp (avoids MUFU bottleneck) -------------
__device__ __forceinline__ float fast_exp(float x) {
    const float L2E = 1.4426950408889634f;
    float t = fmaf(x, L2E, 12582912.0f);           // round-to-nearest via magic
    int   e = __float_as_int(t) - 0x4B400000;      // integer part
    float r = t - 12582912.0f;
    float f = fmaf(x, L2E, -r);                    // f in [-0.5, 0.5]
    float p =            1.3333558e-3f;            // 2^f Taylor (deg 5)
    p = fmaf(p, f, 9.6181291e-3f);
    p = fmaf(p, f, 5.5504109e-2f);
    p = fmaf(p, f, 2.4022651e-1f);
    p = fmaf(p, f, 6.9314718e-1f);
    p = fmaf(p, f, 1.0f);
    return __int_as_float(__float_as_int(p) + (e << 23));
}

// ------------------------- generic fp32 GEMM: C = A@W + bias -----------------
// A [M,K] row-major, W [K,N] row-major. MODE 0: C[M,N] row-major.
// MODE 1: output remapped to [b, h, s, dk] (QKV head-split).
template<int MODE, bool RELU>
__global__ __launch_bounds__(256, 2)
void gemm_kernel(const float* __restrict__ A, const float* __restrict__ W,
                 const float* __restrict__ bias, float* __restrict__ C,
                 int M, int N, int K)
{
    constexpr int BM = 128, BN = 128, BK = 16;
    __shared__ float As[2][BK][BM];
    __shared__ float Ws[2][BK][BN];

    const int tid = threadIdx.x;
    const int bm = blockIdx.y * BM;
    const int bn = blockIdx.x * BN;
    const int tx = tid & 15, ty = tid >> 4;
    const int aRow = tid >> 2, aCol = (tid & 3) << 2;
    const int wRow = tid >> 5, wCol = (tid & 31) << 2;

    const float* Ap = A + (size_t)bm * K;
    const float* Wp = W + bn;

    float acc[8][8];
    #pragma unroll
    for (int i = 0; i < 8; i++)
        #pragma unroll
        for (int j = 0; j < 8; j++) acc[i][j] = 0.f;

    float4 a0, a1, w0, w1;
    // prologue: tile 0
    a0 = *(const float4*)(Ap + (size_t)aRow      * K + aCol);
    a1 = *(const float4*)(Ap + (size_t)(aRow+64) * K + aCol);
    w0 = *(const float4*)(Wp + (size_t)wRow      * N + wCol);
    w1 = *(const float4*)(Wp + (size_t)(wRow+8)  * N + wCol);
    As[0][aCol+0][aRow]    = a0.x; As[0][aCol+1][aRow]    = a0.y;
    As[0][aCol+2][aRow]    = a0.z; As[0][aCol+3][aRow]    = a0.w;
    As[0][aCol+0][aRow+64] = a1.x; As[0][aCol+1][aRow+64] = a1.y;
    As[0][aCol+2][aRow+64] = a1.z; As[0][aCol+3][aRow+64] = a1.w;
    *(float4*)&Ws[0][wRow  ][wCol] = w0;
    *(float4*)&Ws[0][wRow+8][wCol] = w1;
    __syncthreads();

    const int nt = K / BK;
    for (int kt = 0; kt < nt; kt++) {
        const int cur = kt & 1;
        if (kt + 1 < nt) {
            const int k0 = (kt + 1) * BK;
            a0 = *(const float4*)(Ap + (size_t)aRow      * K + k0 + aCol);
            a1 = *(const float4*)(Ap + (size_t)(aRow+64) * K + k0 + aCol);
            w0 = *(const float4*)(Wp + (size_t)(k0+wRow)   * N + wCol);
            w1 = *(const float4*)(Wp + (size_t)(k0+wRow+8) * N + wCol);
        }
        #pragma unroll
        for (int kk = 0; kk < BK; kk++) {
            float rA[8], rB[8];
            *(float4*)&rA[0] = *(const float4*)&As[cur][kk][ty*8];
            *(float4*)&rA[4] = *(const float4*)&As[cur][kk][ty*8+4];
            *(float4*)&rB[0] = *(const float4*)&Ws[cur][kk][tx*8];
            *(float4*)&rB[4] = *(const float4*)&Ws[cur][kk][tx*8+4];
            #pragma unroll
            for (int i = 0; i < 8; i++)
                #pragma unroll
                for (int j = 0; j < 8; j++)
                    acc[i][j] = fmaf(rA[i], rB[j], acc[i][j]);
        }
        if (kt + 1 < nt) {
            const int nx = cur ^ 1;
            As[nx][aCol+0][aRow]    = a0.x; As[nx][aCol+1][aRow]    = a0.y;
            As[nx][aCol+2][aRow]    = a0.z; As[nx][aCol+3][aRow]    = a0.w;
            As[nx][aCol+0][aRow+64] = a1.x; As[nx][aCol+1][aRow+64] = a1.y;
            As[nx][aCol+2][aRow+64] = a1.z; As[nx][aCol+3][aRow+64] = a1.w;
            *(float4*)&Ws[nx][wRow  ][wCol] = w0;
            *(float4*)&Ws[nx][wRow+8][wCol] = w1;
        }
        __syncthreads();
    }

    #pragma unroll
    for (int i = 0; i < 8; i++) {
        const int row = bm + ty*8 + i;
        #pragma unroll
        for (int j = 0; j < 8; j++) {
            const int col = bn + tx*8 + j;
            float vv = acc[i][j] + bias[col];
            if (RELU) vv = vv > 0.f ? vv : 0.f;
            if (MODE == 0) {
                C[(size_t)row * N + col] = vv;
            } else {
                const int b = row >> 11, s = row & (CS - 1);
                const int h = col >> 6,  dk = col & 63;
                C[(((size_t)(b*CH + h))*CS + s)*CDK + dk] = vv;
            }
        }
    }
}

// ------------------------- scores: E = exp( (Q @ K^T) / 8 ) per (b,h) --------
__global__ __launch_bounds__(256, 2)
void scores_kernel()
{
    const int bh = blockIdx.z;
    const int q0 = blockIdx.y << 7;
    const int k0 = blockIdx.x << 7;
    const float* qb = g_q + (size_t)bh * CS * CDK;
    const float* kb = g_k + (size_t)bh * CS * CDK;

    __shared__ float Qs[32][128];
    __shared__ float Ks[32][128];

    const int tid = threadIdx.x;
    const int tx = tid & 15, ty = tid >> 4;
    const int lRow = tid >> 3;
    const int lC4  = (tid & 7) << 2;

    float acc[8][8];
    #pragma unroll
    for (int i = 0; i < 8; i++)
        #pragma unroll
        for (int j = 0; j < 8; j++) acc[i][j] = 0.f;

    for (int d0 = 0; d0 < CDK; d0 += 32) {
        #pragma unroll
        for (int rr = 0; rr < 4; rr++) {
            const int r = lRow + rr * 32;
            float4 qv = *(const float4*)(qb + (size_t)(q0 + r)*CDK + d0 + lC4);
            float4 kv = *(const float4*)(kb + (size_t)(k0 + r)*CDK + d0 + lC4);
            Qs[lC4+0][r] = qv.x; Qs[lC4+1][r] = qv.y;
            Qs[lC4+2][r] = qv.z; Qs[lC4+3][r] = qv.w;
            Ks[lC4+0][r] = kv.x; Ks[lC4+1][r] = kv.y;
            Ks[lC4+2][r] = kv.z; Ks[lC4+3][r] = kv.w;
        }
        __syncthreads();
        #pragma unroll
        for (int kk = 0; kk < 32; kk++) {
            float rQ[8], rK[8];
            *(float4*)&rQ[0] = *(const float4*)&Qs[kk][ty*8];
            *(float4*)&rQ[4] = *(const float4*)&Qs[kk][ty*8+4];
            *(float4*)&rK[0] = *(const float4*)&Ks[kk][tx*8];
            *(float4*)&rK[4] = *(const float4*)&Ks[kk][tx*8+4];
            #pragma unroll
            for (int i = 0; i < 8; i++)
                #pragma unroll
                for (int j = 0; j < 8; j++)
                    acc[i][j] = fmaf(rQ[i], rK[j], acc[i][j]);
        }
        __syncthreads();
    }

    float* Eb = g_E + (size_t)bh * CS * CS;
    #pragma unroll
    for (int i = 0; i < 8; i++) {
        const int q = q0 + ty*8 + i;
        #pragma unroll
        for (int j = 0; j < 8; j++) {
            const int k = k0 + tx*8 + j;
            Eb[(size_t)q * CS + k] = fast_exp(acc[i][j] * 0.125f);
        }
    }
}

// ------------------------- denom: rd[b,q,k] = 1 / sum_h E -------------------
__global__ void denom_kernel()
{
    const size_t idx = (size_t)blockIdx.x * blockDim.x + threadIdx.x;
    const int    b   = (int)(idx / ((size_t)CS * CS));
    const size_t r   = idx % ((size_t)CS * CS);
    const float* e = g_E + ((size_t)b * CH) * CS * CS + r;
    float s = 0.f;
    #pragma unroll
    for (int h = 0; h < CH; h++) s += e[(size_t)h * CS * CS];
    g_rd[idx] = 1.0f / s;
}

// ------------------------- ctx: (E * rd) @ V, output [b,s,h,dk] -------------
__global__ __launch_bounds__(256, 2)
void ctx_kernel()
{
    const int bh = blockIdx.y;
    const int b = bh >> 4, h = bh & 15;
    const int q0 = blockIdx.x << 7;
    const float* eb = g_E  + (size_t)bh * CS * CS;
    const float* rb = g_rd + (size_t)b  * CS * CS;
    const float* vb = g_v  + (size_t)bh * CS * CDK;

    __shared__ float As[32][128];
    __shared__ float Vs[32][64];

    const int tid = threadIdx.x;
    const int tx = tid & 15, ty = tid >> 4;
    const int aRow = tid >> 3, aC4 = (tid & 7) << 2;
    const int vRow = tid >> 4, vC4 = (tid & 15) << 2;

    float acc[8][4];
    #pragma unroll
    for (int i = 0; i < 8; i++)
        #pragma unroll
        for (int j = 0; j < 4; j++) acc[i][j] = 0.f;

    for (int k0 = 0; k0 < CS; k0 += 32) {
        #pragma unroll
        for (int rr = 0; rr < 4; rr++) {
            const int q = q0 + aRow + rr * 32;
            float4 e4 = *(const float4*)(eb + (size_t)q*CS + k0 + aC4);
            float4 r4 = *(const float4*)(rb + (size_t)q*CS + k0 + aC4);
            As[aC4+0][aRow+rr*32] = e4.x * r4.x;
            As[aC4+1][aRow+rr*32] = e4.y * r4.y;
            As[aC4+2][aRow+rr*32] = e4.z * r4.z;
            As[aC4+3][aRow+rr*32] = e4.w * r4.w;
        }
        float4 v0 = *(const float4*)(vb + (size_t)(k0+vRow)   *CDK + vC4);
        float4 v1 = *(const float4*)(vb + (size_t)(k0+vRow+16)*CDK + vC4);
        *(float4*)&Vs[vRow   ][vC4] = v0;
        *(float4*)&Vs[vRow+16][vC4] = v1;
        __syncthreads();
        #pragma unroll
        for (int kk = 0; kk < 32; kk++) {
            float rA[8], rV[4];
            *(float4*)&rA[0] = *(const float4*)&As[kk][ty*8];
            *(float4*)&rA[4] = *(const float4*)&As[kk][ty*8+4];
            *(float4*)&rV[0] = *(const float4*)&Vs[kk][tx*4];
            #pragma unroll
            for (int i = 0; i < 8; i++)
                #pragma unroll
                for (int j = 0; j < 4; j++)
                    acc[i][j] = fmaf(rA[i], rV[j], acc[i][j]);
        }
        __syncthreads();
    }

    #pragma unroll
    for (int i = 0; i < 8; i++) {
        const int q = q0 + ty*8 + i;
        float* outp = g_ctx + (((size_t)(b*CS + q))*CH + h)*CDK + (tx << 2);
        *(float4*)outp = make_float4(acc[i][0], acc[i][1], acc[i][2], acc[i][3]);
    }
}

// ------------------------- residual + LayerNorm -----------------------------
__global__ void ln_kernel(const float* __restrict__ A, const float* __restrict__ Bp,
                          const float* __restrict__ g, const float* __restrict__ be,
                          float* __restrict__ out)
{
    const int row = blockIdx.x;
    const int tid = threadIdx.x;
    const int i0 = tid << 2;
    float4 a  = *(const float4*)(A  + (size_t)row*CD + i0);
    float4 bb = *(const float4*)(Bp + (size_t)row*CD + i0);
    const float v0 = a.x + bb.x, v1 = a.y + bb.y, v2 = a.z + bb.z, v3 = a.w + bb.w;
    float s  = v0 + v1 + v2 + v3;
    float ss = v0*v0 + v1*v1 + v2*v2 + v3*v3;
    #pragma unroll
    for (int o = 16; o; o >>= 1) {
        s  += __shfl_xor_sync(0xffffffffu, s,  o);
        ss += __shfl_xor_sync(0xffffffffu, ss, o);
    }
    __shared__ float sh1[8], sh2[8];
    if ((tid & 31) == 0) { sh1[tid >> 5] = s; sh2[tid >> 5] = ss; }
    __syncthreads();
    s = 0.f; ss = 0.f;
    #pragma unroll
    for (int w = 0; w < 8; w++) { s += sh1[w]; ss += sh2[w]; }
    const float mean = s * (1.0f / CD);
    const float var  = ss * (1.0f / CD) - mean * mean;
    const float rstd = rsqrtf(var + 1e-5f);
    float4 gg = *(const float4*)(g  + i0);
    float4 bt = *(const float4*)(be + i0);
    float4 o4;
    o4.x = (v0 - mean) * rstd * gg.x + bt.x;
    o4.y = (v1 - mean) * rstd * gg.y + bt.y;
    o4.z = (v2 - mean) * rstd * gg.z + bt.z;
    o4.w = (v3 - mean) * rstd * gg.w + bt.w;
    *(float4*)(out + (size_t)row*CD + i0) = o4;
}

// ------------------------- launch -------------------------------------------
extern "C" void kernel_launch(void* const* d_in, const int* in_sizes, int n_in,
                              void* d_out, int out_size)
{
    (void)in_sizes; (void)n_in; (void)out_size;
    const float* x   = (const float*)d_in[0];
    const float* wq  = (const float*)d_in[1];
    const float* bq  = (const float*)d_in[2];
    const float* wk  = (const float*)d_in[3];
    const float* bk  = (const float*)d_in[4];
    const float* wv  = (const float*)d_in[5];
    const float* bv  = (const float*)d_in[6];
    const float* wo  = (const float*)d_in[7];
    const float* bo  = (const float*)d_in[8];
    const float* g1  = (const float*)d_in[9];
    const float* be1 = (const float*)d_in[10];
    const float* w1  = (const float*)d_in[11];
    const float* b1  = (const float*)d_in[12];
    const float* w2  = (const float*)d_in[13];
    const float* b2  = (const float*)d_in[14];
    const float* g2  = (const float*)d_in[15];
    const float* be2 = (const float*)d_in[16];
    float* out = (float*)d_out;

    float *pq, *pk, *pv, *pctx, *pt0, *px1, *pff;
    cudaGetSymbolAddress((void**)&pq,   g_q);
    cudaGetSymbolAddress((void**)&pk,   g_k);
    cudaGetSymbolAddress((void**)&pv,   g_v);
    cudaGetSymbolAddress((void**)&pctx, g_ctx);
    cudaGetSymbolAddress((void**)&pt0,  g_t0);
    cudaGetSymbolAddress((void**)&px1,  g_x1);
    cudaGetSymbolAddress((void**)&pff,  g_ff);

    const dim3 gDD(CD / 128, CM / 128);          // [4096 x 1024] outputs

    // QKV projections -> head-split layout
    gemm_kernel<1, false><<<gDD, 256>>>(x, wq, bq, pq, CM, CD, CD);
    gemm_kernel<1, false><<<gDD, 256>>>(x, wk, bk, pk, CM, CD, CD);
    gemm_kernel<1, false><<<gDD, 256>>>(x, wv, bv, pv, CM, CD, CD);

    // attention with softmax over heads
    scores_kernel<<<dim3(CS/128, CS/128, CB*CH), 256>>>();
    denom_kernel<<<(unsigned)((size_t)CB*CS*CS / 256), 256>>>();
    ctx_kernel<<<dim3(CS/128, CB*CH), 256>>>();

    // output projection + residual LN
    gemm_kernel<0, false><<<gDD, 256>>>(pctx, wo, bo, pt0, CM, CD, CD);
    ln_kernel<<<CM, 256>>>(x, pt0, g1, be1, px1);

    // FFN
    gemm_kernel<0, true ><<<dim3(CDFF/128, CM/128), 256>>>(px1, w1, b1, pff, CM, CDFF, CD);
    gemm_kernel<0, false><<<gDD, 256>>>(pff, w2, b2, pt0, CM, CD, CDFF);
    ln_kernel<<<CM, 256>>>(px1, pt0, g2, be2, out);
}

// round 2
// speedup vs baseline: 1.9563x; 1.9563x over previous
#include <cuda_runtime.h>

constexpr int CB  = 2;
constexpr int CS  = 2048;
constexpr int CD  = 1024;
constexpr int CH  = 16;
constexpr int CDK = 64;
constexpr int CDFF= 4096;
constexpr int CM  = CB * CS;   // 4096

// ------------------------- scratch (device globals) --------------------------
__device__ float g_q  [(size_t)CB*CH*CS*CDK];
__device__ float g_k  [(size_t)CB*CH*CS*CDK];
__device__ float g_v  [(size_t)CB*CH*CS*CDK];
__device__ float g_E  [(size_t)CB*CH*CS*CS];     // exp(scores/8)
__device__ float g_rd [(size_t)CB*CS*CS];        // 1 / sum_h exp
__device__ float g_ctx[(size_t)CM*CD];
__device__ float g_t0 [(size_t)CM*CD];
__device__ float g_x1 [(size_t)CM*CD];
__device__ float g_ff [(size_t)CM*CDFF];

// ------------------------- helpers ------------------------------------------
__device__ __forceinline__ float fast_exp(float x) {
    const float L2E = 1.4426950408889634f;
    float t = fmaf(x, L2E, 12582912.0f);
    int   e = __float_as_int(t) - 0x4B400000;
    float r = t - 12582912.0f;
    float f = fmaf(x, L2E, -r);
    float p =            1.3333558e-3f;
    p = fmaf(p, f, 9.6181291e-3f);
    p = fmaf(p, f, 5.5504109e-2f);
    p = fmaf(p, f, 2.4022651e-1f);
    p = fmaf(p, f, 6.9314718e-1f);
    p = fmaf(p, f, 1.0f);
    return __int_as_float(__float_as_int(p) + (e << 23));
}

__device__ __forceinline__ unsigned f2tf(float x) {
    unsigned u; asm("cvt.rna.tf32.f32 %0, %1;" : "=r"(u) : "f"(x)); return u;
}
__device__ __forceinline__ float tfv(float x) { return __uint_as_float(f2tf(x)); }

__device__ __forceinline__ void mma8(float c[4], const unsigned a[4], const unsigned b[2]) {
    asm volatile("mma.sync.aligned.m16n8k8.row.col.f32.tf32.tf32.f32 "
        "{%0,%1,%2,%3},{%4,%5,%6,%7},{%8,%9},{%0,%1,%2,%3};"
        : "+f"(c[0]), "+f"(c[1]), "+f"(c[2]), "+f"(c[3])
        : "r"(a[0]), "r"(a[1]), "r"(a[2]), "r"(a[3]), "r"(b[0]), "r"(b[1]));
}

// ------------------------- dense GEMM (tf32 tensor core) ---------------------
// A [M,K] rm, W [K,N] rm. MODE 0: C row-major. MODE 1: head-split [b,h,s,dk].
template<int MODE, bool RELU>
__global__ __launch_bounds__(256)
void gemm_tc(const float* __restrict__ A, const float* __restrict__ W,
             const float* __restrict__ bias, float* __restrict__ C,
             int M, int N, int K)
{
    extern __shared__ float sm[];
    float (*As)[136] = (float(*)[136])sm;             // 64 rows: 2 stages x 32 (k-major, m contig)
    float (*Bs)[136] = (float(*)[136])(sm + 64*136);  // 64 rows: 2 stages x 32 (k-major, n contig)

    const int tid = threadIdx.x, lane = tid & 31, w = tid >> 5;
    const int wm = w >> 1, wn = w & 1;
    const int fr = lane >> 2, fc = lane & 3;
    const int bm = blockIdx.y * 128, bn = blockIdx.x * 128;

    const int am = tid & 127, akc0 = tid >> 7;        // A fill: kc = akc0 + 2i
    const int bn4 = tid & 31, bk0 = tid >> 5;         // B fill: k  = bk0 + 8i

    float4 ar[4], br[4];
    auto loadAB = [&](int k0) {
        #pragma unroll
        for (int i = 0; i < 4; i++) {
            ar[i] = *(const float4*)(A + (size_t)(bm + am) * K + k0 + (akc0 + 2*i) * 4);
            br[i] = *(const float4*)(W + (size_t)(k0 + bk0 + 8*i) * N + bn + bn4 * 4);
        }
    };
    auto storeAB = [&](int st) {
        #pragma unroll
        for (int i = 0; i < 4; i++) {
            const int kc = (akc0 + 2*i) * 4;
            As[st*32 + kc + 0][am] = tfv(ar[i].x);
            As[st*32 + kc + 1][am] = tfv(ar[i].y);
            As[st*32 + kc + 2][am] = tfv(ar[i].z);
            As[st*32 + kc + 3][am] = tfv(ar[i].w);
            float4 bb;
            bb.x = tfv(br[i].x); bb.y = tfv(br[i].y); bb.z = tfv(br[i].z); bb.w = tfv(br[i].w);
            *(float4*)&Bs[st*32 + bk0 + 8*i][bn4 * 4] = bb;
        }
    };

    float acc[2][8][4] = {};
    loadAB(0); storeAB(0); __syncthreads();

    const int nt = K / 32;
    for (int kt = 0; kt < nt; kt++) {
        const int cur = kt & 1;
        if (kt + 1 < nt) loadAB((kt + 1) * 32);
        #pragma unroll
        for (int s = 0; s < 4; s++) {
            const int kk = cur * 32 + s * 8;
            unsigned af[2][4], bf[8][2];
            #pragma unroll
            for (int mi = 0; mi < 2; mi++) {
                const int m0 = wm * 32 + mi * 16;
                af[mi][0] = __float_as_uint(As[kk + fc    ][m0 + fr    ]);
                af[mi][1] = __float_as_uint(As[kk + fc    ][m0 + fr + 8]);
                af[mi][2] = __float_as_uint(As[kk + fc + 4][m0 + fr    ]);
                af[mi][3] = __float_as_uint(As[kk + fc + 4][m0 + fr + 8]);
            }
            #pragma unroll
            for (int ni = 0; ni < 8; ni++) {
                const int n0 = wn * 64 + ni * 8;
                bf[ni][0] = __float_as_uint(Bs[kk + fc    ][n0 + fr]);
                bf[ni][1] = __float_as_uint(Bs[kk + fc + 4][n0 + fr]);
            }
            #pragma unroll
            for (int mi = 0; mi < 2; mi++)
                #pragma unroll
                for (int ni = 0; ni < 8; ni++) mma8(acc[mi][ni], af[mi], bf[ni]);
        }
        if (kt + 1 < nt) storeAB((kt + 1) & 1);
        __syncthreads();
    }

    #pragma unroll
    for (int mi = 0; mi < 2; mi++) {
        #pragma unroll
        for (int ni = 0; ni < 8; ni++) {
            const int row = bm + wm * 32 + mi * 16 + fr;
            const int col = bn + wn * 64 + ni * 8 + 2 * fc;
            const float2 b2 = *(const float2*)(bias + col);
            float v0 = acc[mi][ni][0] + b2.x, v1 = acc[mi][ni][1] + b2.y;
            float v2 = acc[mi][ni][2] + b2.x, v3 = acc[mi][ni][3] + b2.y;
            if (RELU) { v0 = fmaxf(v0, 0.f); v1 = fmaxf(v1, 0.f);
                        v2 = fmaxf(v2, 0.f); v3 = fmaxf(v3, 0.f); }
            if (MODE == 0) {
                *(float2*)(C + (size_t)row       * N + col) = make_float2(v0, v1);
                *(float2*)(C + (size_t)(row + 8) * N + col) = make_float2(v2, v3);
            } else {
                const int b = row >> 11, s1 = row & (CS - 1);
                const int h = col >> 6,  dk = col & 63;
                *(float2*)(C + ((((size_t)(b*CH + h))*CS + s1    )*CDK + dk)) = make_float2(v0, v1);
                *(float2*)(C + ((((size_t)(b*CH + h))*CS + s1 + 8)*CDK + dk)) = make_float2(v2, v3);
            }
        }
    }
}

// ------------------------- scores: E = exp((Q@K^T)/8) ------------------------
__global__ __launch_bounds__(256)
void scores_tc()
{
    extern __shared__ float sm[];
    float (*Qs)[136] = (float(*)[136])sm;
    float (*Ks)[136] = (float(*)[136])(sm + 64*136);

    const int tid = threadIdx.x, lane = tid & 31, w = tid >> 5;
    const int wm = w >> 1, wn = w & 1;
    const int fr = lane >> 2, fc = lane & 3;
    const int bh = blockIdx.z;
    const int q0 = blockIdx.y * 128, k0 = blockIdx.x * 128;
    const float* qb = g_q + (size_t)bh * CS * CDK;
    const float* kb = g_k + (size_t)bh * CS * CDK;
    const int am = tid & 127, akc0 = tid >> 7;

    float4 qr[4], kr[4];
    auto loadQK = [&](int d0) {
        #pragma unroll
        for (int i = 0; i < 4; i++) {
            const int dc = (akc0 + 2*i) * 4;
            qr[i] = *(const float4*)(qb + (size_t)(q0 + am) * CDK + d0 + dc);
            kr[i] = *(const float4*)(kb + (size_t)(k0 + am) * CDK + d0 + dc);
        }
    };
    auto storeQK = [&](int st) {
        #pragma unroll
        for (int i = 0; i < 4; i++) {
            const int dc = (akc0 + 2*i) * 4;
            Qs[st*32 + dc + 0][am] = tfv(qr[i].x);
            Qs[st*32 + dc + 1][am] = tfv(qr[i].y);
            Qs[st*32 + dc + 2][am] = tfv(qr[i].z);
            Qs[st*32 + dc + 3][am] = tfv(qr[i].w);
            Ks[st*32 + dc + 0][am] = tfv(kr[i].x);
            Ks[st*32 + dc + 1][am] = tfv(kr[i].y);
            Ks[st*32 + dc + 2][am] = tfv(kr[i].z);
            Ks[st*32 + dc + 3][am] = tfv(kr[i].w);
        }
    };

    float acc[2][8][4] = {};
    loadQK(0); storeQK(0); __syncthreads();
    #pragma unroll
    for (int kt = 0; kt < 2; kt++) {
        if (kt == 0) loadQK(32);
        #pragma unroll
        for (int s = 0; s < 4; s++) {
            const int kk = kt * 32 + s * 8;
            unsigned af[2][4], bf[8][2];
            #pragma unroll
            for (int mi = 0; mi < 2; mi++) {
                const int m0 = wm * 32 + mi * 16;
                af[mi][0] = __float_as_uint(Qs[kk + fc    ][m0 + fr    ]);
                af[mi][1] = __float_as_uint(Qs[kk + fc    ][m0 + fr + 8]);
                af[mi][2] = __float_as_uint(Qs[kk + fc + 4][m0 + fr    ]);
                af[mi][3] = __float_as_uint(Qs[kk + fc + 4][m0 + fr + 8]);
            }
            #pragma unroll
            for (int ni = 0; ni < 8; ni++) {
                const int n0 = wn * 64 + ni * 8;
                bf[ni][0] = __float_as_uint(Ks[kk + fc    ][n0 + fr]);
                bf[ni][1] = __float_as_uint(Ks[kk + fc + 4][n0 + fr]);
            }
            #pragma unroll
            for (int mi = 0; mi < 2; mi++)
                #pragma unroll
                for (int ni = 0; ni < 8; ni++) mma8(acc[mi][ni], af[mi], bf[ni]);
        }
        if (kt == 0) storeQK(1);
        __syncthreads();
    }

    float* Eb = g_E + (size_t)bh * CS * CS;
    #pragma unroll
    for (int mi = 0; mi < 2; mi++) {
        #pragma unroll
        for (int ni = 0; ni < 8; ni++) {
            const int q = q0 + wm * 32 + mi * 16 + fr;
            const int k = k0 + wn * 64 + ni * 8 + 2 * fc;
            float e0 = fast_exp(acc[mi][ni][0] * 0.125f);
            float e1 = fast_exp(acc[mi][ni][1] * 0.125f);
            float e2 = fast_exp(acc[mi][ni][2] * 0.125f);
            float e3 = fast_exp(acc[mi][ni][3] * 0.125f);
            *(float2*)(Eb + (size_t)q       * CS + k) = make_float2(e0, e1);
            *(float2*)(Eb + (size_t)(q + 8) * CS + k) = make_float2(e2, e3);
        }
    }
}

// ------------------------- denom: rd = 1 / sum_h E (float4) ------------------
__global__ void denom_tc()
{
    const size_t idx = (size_t)blockIdx.x * blockDim.x + threadIdx.x;  // over CB*CS*CS/4
    const size_t plane4 = (size_t)CS * CS / 4;
    const int b = (int)(idx / plane4);
    const size_t r4 = idx % plane4;
    const float4* e = (const float4*)g_E + (size_t)b * CH * plane4 + r4;
    float4 s = make_float4(0.f, 0.f, 0.f, 0.f);
    #pragma unroll
    for (int h = 0; h < CH; h++) {
        float4 t = e[(size_t)h * plane4];
        s.x += t.x; s.y += t.y; s.z += t.z; s.w += t.w;
    }
    float4 o;
    o.x = 1.0f / s.x; o.y = 1.0f / s.y; o.z = 1.0f / s.z; o.w = 1.0f / s.w;
    ((float4*)g_rd)[idx] = o;
}

// ------------------------- ctx: (E*rd) @ V -> [b,s,h,dk] ---------------------
__global__ __launch_bounds__(256)
void ctx_tc()
{
    extern __shared__ float sm[];
    float (*Ps)[136] = (float(*)[136])sm;               // 64 rows (2 x 32), m contig
    float (*Vs)[72]  = (float(*)[72])(sm + 64*136);     // 64 rows (2 x 32), n contig

    const int tid = threadIdx.x, lane = tid & 31, w = tid >> 5;
    const int wm = w >> 1, wn = w & 1;
    const int fr = lane >> 2, fc = lane & 3;
    const int bh = blockIdx.y;
    const int b = bh >> 4, h = bh & 15;
    const int q0 = blockIdx.x * 128;
    const float* eb = g_E  + (size_t)bh * CS * CS;
    const float* rb = g_rd + (size_t)b  * CS * CS;
    const float* vb = g_v  + (size_t)bh * CS * CDK;

    const int am = tid & 127, akc0 = tid >> 7;
    const int vn4 = tid & 15, vk0 = tid >> 4;

    float4 er[4], rr[4], vr[2];
    auto loadT = [&](int k0t) {
        #pragma unroll
        for (int i = 0; i < 4; i++) {
            const int kc = (akc0 + 2*i) * 4;
            er[i] = *(const float4*)(eb + (size_t)(q0 + am) * CS + k0t + kc);
            rr[i] = *(const float4*)(rb + (size_t)(q0 + am) * CS + k0t + kc);
        }
        #pragma unroll
        for (int i = 0; i < 2; i++)
            vr[i] = *(const float4*)(vb + (size_t)(k0t + vk0 + 16*i) * CDK + vn4 * 4);
    };
    auto storeT = [&](int st) {
        #pragma unroll
        for (int i = 0; i < 4; i++) {
            const int kc = (akc0 + 2*i) * 4;
            Ps[st*32 + kc + 0][am] = tfv(er[i].x * rr[i].x);
            Ps[st*32 + kc + 1][am] = tfv(er[i].y * rr[i].y);
            Ps[st*32 + kc + 2][am] = tfv(er[i].z * rr[i].z);
            Ps[st*32 + kc + 3][am] = tfv(er[i].w * rr[i].w);
        }
        #pragma unroll
        for (int i = 0; i < 2; i++) {
            float4 vv;
            vv.x = tfv(vr[i].x); vv.y = tfv(vr[i].y); vv.z = tfv(vr[i].z); vv.w = tfv(vr[i].w);
            *(float4*)&Vs[st*32 + vk0 + 16*i][vn4 * 4] = vv;
        }
    };

    float acc[2][4][4] = {};
    loadT(0); storeT(0); __syncthreads();

    for (int kt = 0; kt < CS / 32; kt++) {
        const int cur = kt & 1;
        if (kt + 1 < CS / 32) loadT((kt + 1) * 32);
        #pragma unroll
        for (int s = 0; s < 4; s++) {
            const int kk = cur * 32 + s * 8;
            unsigned af[2][4], bf[4][2];
            #pragma unroll
            for (int mi = 0; mi < 2; mi++) {
                const int m0 = wm * 32 + mi * 16;
                af[mi][0] = __float_as_uint(Ps[kk + fc    ][m0 + fr    ]);
                af[mi][1] = __float_as_uint(Ps[kk + fc    ][m0 + fr + 8]);
                af[mi][2] = __float_as_uint(Ps[kk + fc + 4][m0 + fr    ]);
                af[mi][3] = __float_as_uint(Ps[kk + fc + 4][m0 + fr + 8]);
            }
            #pragma unroll
            for (int ni = 0; ni < 4; ni++) {
                const int n0 = wn * 32 + ni * 8;
                bf[ni][0] = __float_as_uint(Vs[kk + fc    ][n0 + fr]);
                bf[ni][1] = __float_as_uint(Vs[kk + fc + 4][n0 + fr]);
            }
            #pragma unroll
            for (int mi = 0; mi < 2; mi++)
                #pragma unroll
                for (int ni = 0; ni < 4; ni++) mma8(acc[mi][ni], af[mi], bf[ni]);
        }
        if (kt + 1 < CS / 32) storeT(cur ^ 1);
        __syncthreads();
    }

    #pragma unroll
    for (int mi = 0; mi < 2; mi++) {
        #pragma unroll
        for (int ni = 0; ni < 4; ni++) {
            const int q = q0 + wm * 32 + mi * 16 + fr;
            const int n = wn * 32 + ni * 8 + 2 * fc;
            float* p0 = g_ctx + (((size_t)(b * CS + q    )) * CH + h) * CDK + n;
            float* p1 = g_ctx + (((size_t)(b * CS + q + 8)) * CH + h) * CDK + n;
            *(float2*)p0 = make_float2(acc[mi][ni][0], acc[mi][ni][1]);
            *(float2*)p1 = make_float2(acc[mi][ni][2], acc[mi][ni][3]);
        }
    }
}

// ------------------------- residual + LayerNorm ------------------------------
__global__ void ln_kernel(const float* __restrict__ A, const float* __restrict__ Bp,
                          const float* __restrict__ g, const float* __restrict__ be,
                          float* __restrict__ out)
{
    const int row = blockIdx.x;
    const int tid = threadIdx.x;
    const int i0 = tid << 2;
    float4 a  = *(const float4*)(A  + (size_t)row*CD + i0);
    float4 bb = *(const float4*)(Bp + (size_t)row*CD + i0);
    const float v0 = a.x + bb.x, v1 = a.y + bb.y, v2 = a.z + bb.z, v3 = a.w + bb.w;
    float s  = v0 + v1 + v2 + v3;
    float ss = v0*v0 + v1*v1 + v2*v2 + v3*v3;
    #pragma unroll
    for (int o = 16; o; o >>= 1) {
        s  += __shfl_xor_sync(0xffffffffu, s,  o);
        ss += __shfl_xor_sync(0xffffffffu, ss, o);
    }
    __shared__ float sh1[8], sh2[8];
    if ((tid & 31) == 0) { sh1[tid >> 5] = s; sh2[tid >> 5] = ss; }
    __syncthreads();
    s = 0.f; ss = 0.f;
    #pragma unroll
    for (int w = 0; w < 8; w++) { s += sh1[w]; ss += sh2[w]; }
    const float mean = s * (1.0f / CD);
    const float var  = ss * (1.0f / CD) - mean * mean;
    const float rstd = rsqrtf(var + 1e-5f);
    float4 gg = *(const float4*)(g  + i0);
    float4 bt = *(const float4*)(be + i0);
    float4 o4;
    o4.x = (v0 - mean) * rstd * gg.x + bt.x;
    o4.y = (v1 - mean) * rstd * gg.y + bt.y;
    o4.z = (v2 - mean) * rstd * gg.z + bt.z;
    o4.w = (v3 - mean) * rstd * gg.w + bt.w;
    *(float4*)(out + (size_t)row*CD + i0) = o4;
}

// ------------------------- launch -------------------------------------------
extern "C" void kernel_launch(void* const* d_in, const int* in_sizes, int n_in,
                              void* d_out, int out_size)
{
    (void)in_sizes; (void)n_in; (void)out_size;
    const float* x   = (const float*)d_in[0];
    const float* wq  = (const float*)d_in[1];
    const float* bq  = (const float*)d_in[2];
    const float* wk  = (const float*)d_in[3];
    const float* bk  = (const float*)d_in[4];
    const float* wv  = (const float*)d_in[5];
    const float* bv  = (const float*)d_in[6];
    const float* wo  = (const float*)d_in[7];
    const float* bo  = (const float*)d_in[8];
    const float* g1  = (const float*)d_in[9];
    const float* be1 = (const float*)d_in[10];
    const float* w1  = (const float*)d_in[11];
    const float* b1  = (const float*)d_in[12];
    const float* w2  = (const float*)d_in[13];
    const float* b2  = (const float*)d_in[14];
    const float* g2  = (const float*)d_in[15];
    const float* be2 = (const float*)d_in[16];
    float* out = (float*)d_out;

    float *pq, *pk, *pv, *pctx, *pt0, *px1, *pff;
    cudaGetSymbolAddress((void**)&pq,   g_q);
    cudaGetSymbolAddress((void**)&pk,   g_k);
    cudaGetSymbolAddress((void**)&pv,   g_v);
    cudaGetSymbolAddress((void**)&pctx, g_ctx);
    cudaGetSymbolAddress((void**)&pt0,  g_t0);
    cudaGetSymbolAddress((void**)&px1,  g_x1);
    cudaGetSymbolAddress((void**)&pff,  g_ff);

    const int SMEM_G = 2 * 64 * 136 * 4;                 // 69632
    const int SMEM_S = 2 * 64 * 136 * 4;                 // 69632
    const int SMEM_C = (64 * 136 + 64 * 72) * 4;         // 53248
    cudaFuncSetAttribute(gemm_tc<1,false>, cudaFuncAttributeMaxDynamicSharedMemorySize, SMEM_G);
    cudaFuncSetAttribute(gemm_tc<0,false>, cudaFuncAttributeMaxDynamicSharedMemorySize, SMEM_G);
    cudaFuncSetAttribute(gemm_tc<0,true >, cudaFuncAttributeMaxDynamicSharedMemorySize, SMEM_G);
    cudaFuncSetAttribute(scores_tc, cudaFuncAttributeMaxDynamicSharedMemorySize, SMEM_S);
    cudaFuncSetAttribute(ctx_tc,    cudaFuncAttributeMaxDynamicSharedMemorySize, SMEM_C);

    const dim3 gDD(CD / 128, CM / 128);

    // QKV projections -> head-split layout
    gemm_tc<1, false><<<gDD, 256, SMEM_G>>>(x, wq, bq, pq, CM, CD, CD);
    gemm_tc<1, false><<<gDD, 256, SMEM_G>>>(x, wk, bk, pk, CM, CD, CD);
    gemm_tc<1, false><<<gDD, 256, SMEM_G>>>(x, wv, bv, pv, CM, CD, CD);

    // attention with softmax over heads
    scores_tc<<<dim3(CS/128, CS/128, CB*CH), 256, SMEM_S>>>();
    denom_tc<<<(unsigned)((size_t)CB*CS*CS/4/256), 256>>>();
    ctx_tc<<<dim3(CS/128, CB*CH), 256, SMEM_C>>>();

    // output projection + residual LN
    gemm_tc<0, false><<<gDD, 256, SMEM_G>>>(pctx, wo, bo, pt0, CM, CD, CD);
    ln_kernel<<<CM, 256>>>(x, pt0, g1, be1, px1);

    // FFN
    gemm_tc<0, true ><<<dim3(CDFF/128, CM/128), 256, SMEM_G>>>(px1, w1, b1, pff, CM, CDFF, CD);
    gemm_tc<0, false><<<gDD, 256, SMEM_G>>>(pff, w2, b2, pt0, CM, CD, CDFF);
    ln_kernel<<<CM, 256>>>(px1, pt0, g2, be2, out);
}

// round 4
// speedup vs baseline: 1.9704x; 1.0072x over previous
#include <cuda_runtime.h>
#include <cstdint>

constexpr int CB  = 2;
constexpr int CS  = 2048;
constexpr int CD  = 1024;
constexpr int CH  = 16;
constexpr int CDK = 64;
constexpr int CDFF= 4096;
constexpr int CM  = CB * CS;   // 4096

// ------------------------- scratch (device globals) --------------------------
__device__ float g_q  [(size_t)CB*CH*CS*CDK];
__device__ float g_k  [(size_t)CB*CH*CS*CDK];
__device__ float g_v  [(size_t)CB*CH*CS*CDK];
__device__ float g_E  [(size_t)CB*CH*CS*CS];
__device__ float g_rd [(size_t)CB*CS*CS];
__device__ float g_ctx[(size_t)CM*CD];
__device__ float g_t0 [(size_t)CM*CD];
__device__ float g_x1 [(size_t)CM*CD];
__device__ float g_ff [(size_t)CM*CDFF];

// ------------------------- helpers ------------------------------------------
__device__ __forceinline__ float fast_exp(float x) {
    const float L2E = 1.4426950408889634f;
    float t = fmaf(x, L2E, 12582912.0f);
    int   e = __float_as_int(t) - 0x4B400000;
    float r = t - 12582912.0f;
    float f = fmaf(x, L2E, -r);
    float p =            1.3333558e-3f;
    p = fmaf(p, f, 9.6181291e-3f);
    p = fmaf(p, f, 5.5504109e-2f);
    p = fmaf(p, f, 2.4022651e-1f);
    p = fmaf(p, f, 6.9314718e-1f);
    p = fmaf(p, f, 1.0f);
    return __int_as_float(__float_as_int(p) + (e << 23));
}
__device__ __forceinline__ unsigned f2tf(float x) {
    unsigned u; asm("cvt.rna.tf32.f32 %0, %1;" : "=r"(u) : "f"(x)); return u;
}
__device__ __forceinline__ uint32_t smem_u32(const void* p) {
    uint32_t a;
    asm("{ .reg .u64 t; cvta.to.shared.u64 t, %1; cvt.u32.u64 %0, t; }" : "=r"(a) : "l"(p));
    return a;
}
__device__ __forceinline__ void cp16(uint32_t dst, const float* src) {
    asm volatile("cp.async.cg.shared.global [%0], [%1], 16;"
                 :: "r"(dst), "l"((unsigned long long)__cvta_generic_to_global(src)));
}
#define CP_COMMIT() asm volatile("cp.async.commit_group;" ::: "memory")
#define CP_WAIT(n)  asm volatile("cp.async.wait_group %0;" :: "n"(n) : "memory")

__device__ __forceinline__ void mma8(float c[4], const unsigned a[4], const unsigned b[2]) {
    asm volatile("mma.sync.aligned.m16n8k8.row.col.f32.tf32.tf32.f32 "
        "{%0,%1,%2,%3},{%4,%5,%6,%7},{%8,%9},{%0,%1,%2,%3};"
        : "+f"(c[0]), "+f"(c[1]), "+f"(c[2]), "+f"(c[3])
        : "r"(a[0]), "r"(a[1]), "r"(a[2]), "r"(a[3]), "r"(b[0]), "r"(b[1]));
}

// ======================= dense GEMM: cp.async 3-stage ========================
// A [M,K] rm, W [K,N] rm. Tile 128x128x32. smem: A [128][36], B [32][132].
template<int MODE, bool RELU>
__global__ __launch_bounds__(256, 2)
void gemm_cp(const float* __restrict__ A, const float* __restrict__ W,
             const float* __restrict__ bias, float* __restrict__ C,
             int M, int N, int K)
{
    constexpr int ASTR = 36, BSTR = 132;
    constexpr int ASZ = 128 * ASTR, BSZ = 32 * BSTR, STG = ASZ + BSZ;
    extern __shared__ float sm[];
    const uint32_t smb = smem_u32(sm);

    const int tid = threadIdx.x, wid = tid >> 5, lane = tid & 31;
    const int wm = wid >> 1, wn = wid & 1;
    const int fr = lane >> 2, fc = lane & 3;
    const int bm = blockIdx.y * 128, bn = blockIdx.x * 128;

    auto issue = [&](int kt) {
        const int st = kt % 3;
        const float* Asrc = A + (size_t)bm * K + (size_t)kt * 32;
        const float* Bsrc = W + (size_t)kt * 32 * N + bn;
        #pragma unroll
        for (int i = 0; i < 4; i++) {
            const int c = i * 256 + tid;
            const int r = c >> 3, c4 = (c & 7) * 4;
            cp16(smb + (st * STG + r * ASTR + c4) * 4, Asrc + (size_t)r * K + c4);
        }
        #pragma unroll
        for (int i = 0; i < 4; i++) {
            const int c = i * 256 + tid;
            const int kk = c >> 5, n4 = (c & 31) * 4;
            cp16(smb + (st * STG + ASZ + kk * BSTR + n4) * 4, Bsrc + (size_t)kk * N + n4);
        }
    };

    float acc[2][8][4] = {};
    const int nt = K / 32;
    issue(0); CP_COMMIT();
    issue(1); CP_COMMIT();

    for (int kt = 0; kt < nt; kt++) {
        CP_WAIT(1);
        __syncthreads();
        if (kt + 2 < nt) issue(kt + 2);
        CP_COMMIT();

        const float* Sa = sm + (kt % 3) * STG;
        const float* Sb = Sa + ASZ;
        #pragma unroll
        for (int s8 = 0; s8 < 4; s8++) {
            const int kk = s8 * 8;
            unsigned af[2][4], bf[8][2];
            #pragma unroll
            for (int mi = 0; mi < 2; mi++) {
                const int m0 = wm * 32 + mi * 16;
                af[mi][0] = f2tf(Sa[(m0 + fr    ) * ASTR + kk + fc    ]);
                af[mi][1] = f2tf(Sa[(m0 + fr + 8) * ASTR + kk + fc    ]);
                af[mi][2] = f2tf(Sa[(m0 + fr    ) * ASTR + kk + fc + 4]);
                af[mi][3] = f2tf(Sa[(m0 + fr + 8) * ASTR + kk + fc + 4]);
            }
            #pragma unroll
            for (int ni = 0; ni < 8; ni++) {
                const int n0 = wn * 64 + ni * 8;
                bf[ni][0] = f2tf(Sb[(kk + fc    ) * BSTR + n0 + fr]);
                bf[ni][1] = f2tf(Sb[(kk + fc + 4) * BSTR + n0 + fr]);
            }
            #pragma unroll
            for (int mi = 0; mi < 2; mi++)
                #pragma unroll
                for (int ni = 0; ni < 8; ni++) mma8(acc[mi][ni], af[mi], bf[ni]);
        }
    }

    #pragma unroll
    for (int mi = 0; mi < 2; mi++) {
        #pragma unroll
        for (int ni = 0; ni < 8; ni++) {
            const int row = bm + wm * 32 + mi * 16 + fr;
            const int col = bn + wn * 64 + ni * 8 + 2 * fc;
            const float2 b2 = *(const float2*)(bias + col);
            float v0 = acc[mi][ni][0] + b2.x, v1 = acc[mi][ni][1] + b2.y;
            float v2 = acc[mi][ni][2] + b2.x, v3 = acc[mi][ni][3] + b2.y;
            if (RELU) { v0 = fmaxf(v0, 0.f); v1 = fmaxf(v1, 0.f);
                        v2 = fmaxf(v2, 0.f); v3 = fmaxf(v3, 0.f); }
            if (MODE == 0) {
                *(float2*)(C + (size_t)row       * N + col) = make_float2(v0, v1);
                *(float2*)(C + (size_t)(row + 8) * N + col) = make_float2(v2, v3);
            } else {
                const int b = row >> 11, s1 = row & (CS - 1);
                const int h = col >> 6,  dk = col & 63;
                *(float2*)(C + ((((size_t)(b*CH + h))*CS + s1    )*CDK + dk)) = make_float2(v0, v1);
                *(float2*)(C + ((((size_t)(b*CH + h))*CS + s1 + 8)*CDK + dk)) = make_float2(v2, v3);
            }
        }
    }
}

// ======================= scores: cp.async, E = exp((Q@K^T)/8) ================
// Q [m][dk], Kmat [n][dk]. smem per stage: Q [128][36] + K [128][36]. nt=2.
__global__ __launch_bounds__(256, 2)
void scores_cp()
{
    constexpr int QSTR = 36;
    constexpr int QSZ = 128 * QSTR, STG = 2 * QSZ;
    extern __shared__ float sm[];
    const uint32_t smb = smem_u32(sm);

    const int tid = threadIdx.x, wid = tid >> 5, lane = tid & 31;
    const int wm = wid >> 1, wn = wid & 1;
    const int fr = lane >> 2, fc = lane & 3;
    const int bh = blockIdx.z;
    const int q0 = blockIdx.y * 128, k0 = blockIdx.x * 128;
    const float* qb = g_q + (size_t)bh * CS * CDK;
    const float* kb = g_k + (size_t)bh * CS * CDK;

    auto issue = [&](int kt) {
        #pragma unroll
        for (int i = 0; i < 4; i++) {
            const int c = i * 256 + tid;
            const int r = c >> 3, c4 = (c & 7) * 4;
            cp16(smb + (kt * STG + r * QSTR + c4) * 4,
                 qb + (size_t)(q0 + r) * CDK + kt * 32 + c4);
            cp16(smb + (kt * STG + QSZ + r * QSTR + c4) * 4,
                 kb + (size_t)(k0 + r) * CDK + kt * 32 + c4);
        }
    };

    float acc[2][8][4] = {};
    issue(0); CP_COMMIT();
    issue(1); CP_COMMIT();

    #pragma unroll
    for (int kt = 0; kt < 2; kt++) {
        if (kt == 0) { CP_WAIT(1); } else { CP_WAIT(0); }
        __syncthreads();
        const float* Sq = sm + kt * STG;
        const float* Sk = Sq + QSZ;
        #pragma unroll
        for (int s8 = 0; s8 < 4; s8++) {
            const int kk = s8 * 8;
            unsigned af[2][4], bf[8][2];
            #pragma unroll
            for (int mi = 0; mi < 2; mi++) {
                const int m0 = wm * 32 + mi * 16;
                af[mi][0] = f2tf(Sq[(m0 + fr    ) * QSTR + kk + fc    ]);
                af[mi][1] = f2tf(Sq[(m0 + fr + 8) * QSTR + kk + fc    ]);
                af[mi][2] = f2tf(Sq[(m0 + fr    ) * QSTR + kk + fc + 4]);
                af[mi][3] = f2tf(Sq[(m0 + fr + 8) * QSTR + kk + fc + 4]);
            }
            #pragma unroll
            for (int ni = 0; ni < 8; ni++) {
                const int n0 = wn * 64 + ni * 8;
                bf[ni][0] = f2tf(Sk[(n0 + fr) * QSTR + kk + fc    ]);
                bf[ni][1] = f2tf(Sk[(n0 + fr) * QSTR + kk + fc + 4]);
            }
            #pragma unroll
            for (int mi = 0; mi < 2; mi++)
                #pragma unroll
                for (int ni = 0; ni < 8; ni++) mma8(acc[mi][ni], af[mi], bf[ni]);
        }
    }

    float* Eb = g_E + (size_t)bh * CS * CS;
    #pragma unroll
    for (int mi = 0; mi < 2; mi++) {
        #pragma unroll
        for (int ni = 0; ni < 8; ni++) {
            const int q = q0 + wm * 32 + mi * 16 + fr;
            const int k = k0 + wn * 64 + ni * 8 + 2 * fc;
            float e0 = fast_exp(acc[mi][ni][0] * 0.125f);
            float e1 = fast_exp(acc[mi][ni][1] * 0.125f);
            float e2 = fast_exp(acc[mi][ni][2] * 0.125f);
            float e3 = fast_exp(acc[mi][ni][3] * 0.125f);
            *(float2*)(Eb + (size_t)q       * CS + k) = make_float2(e0, e1);
            *(float2*)(Eb + (size_t)(q + 8) * CS + k) = make_float2(e2, e3);
        }
    }
}

// ------------------------- denom: rd = 1 / sum_h E ---------------------------
__global__ void denom_tc()
{
    const size_t idx = (size_t)blockIdx.x * blockDim.x + threadIdx.x;
    const size_t plane4 = (size_t)CS * CS / 4;
    const int b = (int)(idx / plane4);
    const size_t r4 = idx % plane4;
    const float4* e = (const float4*)g_E + (size_t)b * CH * plane4 + r4;
    float4 s = make_float4(0.f, 0.f, 0.f, 0.f);
    #pragma unroll
    for (int h = 0; h < CH; h++) {
        float4 t = e[(size_t)h * plane4];
        s.x += t.x; s.y += t.y; s.z += t.z; s.w += t.w;
    }
    float4 o;
    o.x = 1.0f / s.x; o.y = 1.0f / s.y; o.z = 1.0f / s.z; o.w = 1.0f / s.w;
    ((float4*)g_rd)[idx] = o;
}

// ======================= ctx: (E*rd) @ V, cp.async 2-stage ===================
// smem per stage: E [128][36], rd [128][36], V [32][68]. nt=64.
__global__ __launch_bounds__(256, 2)
void ctx_cp()
{
    constexpr int ESTR = 36, VSTR = 68;
    constexpr int ESZ = 128 * ESTR, VSZ = 32 * VSTR;
    constexpr int STG = 2 * ESZ + VSZ;
    extern __shared__ float sm[];
    const uint32_t smb = smem_u32(sm);

    const int tid = threadIdx.x, wid = tid >> 5, lane = tid & 31;
    const int wm = wid >> 1, wn = wid & 1;
    const int fr = lane >> 2, fc = lane & 3;
    const int bh = blockIdx.y;
    const int b = bh >> 4, h = bh & 15;
    const int q0 = blockIdx.x * 128;
    const float* eb = g_E  + (size_t)bh * CS * CS;
    const float* rb = g_rd + (size_t)b  * CS * CS;
    const float* vb = g_v  + (size_t)bh * CS * CDK;

    auto issue = [&](int kt) {
        const int st = kt & 1;
        const int kbase = kt * 32;
        #pragma unroll
        for (int i = 0; i < 4; i++) {
            const int c = i * 256 + tid;
            const int r = c >> 3, c4 = (c & 7) * 4;
            cp16(smb + (st * STG + r * ESTR + c4) * 4,
                 eb + (size_t)(q0 + r) * CS + kbase + c4);
            cp16(smb + (st * STG + ESZ + r * ESTR + c4) * 4,
                 rb + (size_t)(q0 + r) * CS + kbase + c4);
        }
        #pragma unroll
        for (int i = 0; i < 2; i++) {
            const int c = i * 256 + tid;
            const int kk = c >> 4, n4 = (c & 15) * 4;
            cp16(smb + (st * STG + 2 * ESZ + kk * VSTR + n4) * 4,
                 vb + (size_t)(kbase + kk) * CDK + n4);
        }
    };

    float acc[2][4][4] = {};
    const int nt = CS / 32;
    issue(0); CP_COMMIT();

    for (int kt = 0; kt < nt; kt++) {
        CP_WAIT(0);
        __syncthreads();
        if (kt + 1 < nt) issue(kt + 1);
        CP_COMMIT();

        const float* Se = sm + (kt & 1) * STG;
        const float* Sr = Se + ESZ;
        const float* Sv = Sr + ESZ;
        #pragma unroll
        for (int s8 = 0; s8 < 4; s8++) {
            const int kk = s8 * 8;
            unsigned af[2][4], bf[4][2];
            #pragma unroll
            for (int mi = 0; mi < 2; mi++) {
                const int m0 = wm * 32 + mi * 16;
                const int i00 = (m0 + fr    ) * ESTR + kk + fc;
                const int i10 = (m0 + fr + 8) * ESTR + kk + fc;
                af[mi][0] = f2tf(Se[i00    ] * Sr[i00    ]);
                af[mi][1] = f2tf(Se[i10    ] * Sr[i10    ]);
                af[mi][2] = f2tf(Se[i00 + 4] * Sr[i00 + 4]);
                af[mi][3] = f2tf(Se[i10 + 4] * Sr[i10 + 4]);
            }
            #pragma unroll
            for (int ni = 0; ni < 4; ni++) {
                const int n0 = wn * 32 + ni * 8;
                bf[ni][0] = f2tf(Sv[(kk + fc    ) * VSTR + n0 + fr]);
                bf[ni][1] = f2tf(Sv[(kk + fc + 4) * VSTR + n0 + fr]);
            }
            #pragma unroll
            for (int mi = 0; mi < 2; mi++)
                #pragma unroll
                for (int ni = 0; ni < 4; ni++) mma8(acc[mi][ni], af[mi], bf[ni]);
        }
    }

    #pragma unroll
    for (int mi = 0; mi < 2; mi++) {
        #pragma unroll
        for (int ni = 0; ni < 4; ni++) {
            const int q = q0 + wm * 32 + mi * 16 + fr;
            const int n = wn * 32 + ni * 8 + 2 * fc;
            float* p0 = g_ctx + (((size_t)(b * CS + q    )) * CH + h) * CDK + n;
            float* p1 = g_ctx + (((size_t)(b * CS + q + 8)) * CH + h) * CDK + n;
            *(float2*)p0 = make_float2(acc[mi][ni][0], acc[mi][ni][1]);
            *(float2*)p1 = make_float2(acc[mi][ni][2], acc[mi][ni][3]);
        }
    }
}

// ------------------------- residual + LayerNorm ------------------------------
__global__ void ln_kernel(const float* __restrict__ A, const float* __restrict__ Bp,
                          const float* __restrict__ g, const float* __restrict__ be,
                          float* __restrict__ out)
{
    const int row = blockIdx.x;
    const int tid = threadIdx.x;
    const int i0 = tid << 2;
    float4 a  = *(const float4*)(A  + (size_t)row*CD + i0);
    float4 bb = *(const float4*)(Bp + (size_t)row*CD + i0);
    const float v0 = a.x + bb.x, v1 = a.y + bb.y, v2 = a.z + bb.z, v3 = a.w + bb.w;
    float s  = v0 + v1 + v2 + v3;
    float ss = v0*v0 + v1*v1 + v2*v2 + v3*v3;
    #pragma unroll
    for (int o = 16; o; o >>= 1) {
        s  += __shfl_xor_sync(0xffffffffu, s,  o);
        ss += __shfl_xor_sync(0xffffffffu, ss, o);
    }
    __shared__ float sh1[8], sh2[8];
    if ((tid & 31) == 0) { sh1[tid >> 5] = s; sh2[tid >> 5] = ss; }
    __syncthreads();
    s = 0.f; ss = 0.f;
    #pragma unroll
    for (int w = 0; w < 8; w++) { s += sh1[w]; ss += sh2[w]; }
    const float mean = s * (1.0f / CD);
    const float var  = ss * (1.0f / CD) - mean * mean;
    const float rstd = rsqrtf(var + 1e-5f);
    float4 gg = *(const float4*)(g  + i0);
    float4 bt = *(const float4*)(be + i0);
    float4 o4;
    o4.x = (v0 - mean) * rstd * gg.x + bt.x;
    o4.y = (v1 - mean) * rstd * gg.y + bt.y;
    o4.z = (v2 - mean) * rstd * gg.z + bt.z;
    o4.w = (v3 - mean) * rstd * gg.w + bt.w;
    *(float4*)(out + (size_t)row*CD + i0) = o4;
}

// ------------------------- launch -------------------------------------------
extern "C" void kernel_launch(void* const* d_in, const int* in_sizes, int n_in,
                              void* d_out, int out_size)
{
    (void)in_sizes; (void)n_in; (void)out_size;
    const float* x   = (const float*)d_in[0];
    const float* wq  = (const float*)d_in[1];
    const float* bq  = (const float*)d_in[2];
    const float* wk  = (const float*)d_in[3];
    const float* bk  = (const float*)d_in[4];
    const float* wv  = (const float*)d_in[5];
    const float* bv  = (const float*)d_in[6];
    const float* wo  = (const float*)d_in[7];
    const float* bo  = (const float*)d_in[8];
    const float* g1  = (const float*)d_in[9];
    const float* be1 = (const float*)d_in[10];
    const float* w1  = (const float*)d_in[11];
    const float* b1  = (const float*)d_in[12];
    const float* w2  = (const float*)d_in[13];
    const float* b2  = (const float*)d_in[14];
    const float* g2  = (const float*)d_in[15];
    const float* be2 = (const float*)d_in[16];
    float* out = (float*)d_out;

    float *pq, *pk, *pv, *pctx, *pt0, *px1, *pff;
    cudaGetSymbolAddress((void**)&pq,   g_q);
    cudaGetSymbolAddress((void**)&pk,   g_k);
    cudaGetSymbolAddress((void**)&pv,   g_v);
    cudaGetSymbolAddress((void**)&pctx, g_ctx);
    cudaGetSymbolAddress((void**)&pt0,  g_t0);
    cudaGetSymbolAddress((void**)&px1,  g_x1);
    cudaGetSymbolAddress((void**)&pff,  g_ff);

    const int SMEM_G = 3 * (128*36 + 32*132) * 4;          // 105984
    const int SMEM_S = 2 * (2 * 128*36) * 4;               // 73728
    const int SMEM_C = 2 * (2 * 128*36 + 32*68) * 4;       // 91136
    cudaFuncSetAttribute(gemm_cp<1,false>, cudaFuncAttributeMaxDynamicSharedMemorySize, SMEM_G);
    cudaFuncSetAttribute(gemm_cp<0,false>, cudaFuncAttributeMaxDynamicSharedMemorySize, SMEM_G);
    cudaFuncSetAttribute(gemm_cp<0,true >, cudaFuncAttributeMaxDynamicSharedMemorySize, SMEM_G);
    cudaFuncSetAttribute(scores_cp, cudaFuncAttributeMaxDynamicSharedMemorySize, SMEM_S);
    cudaFuncSetAttribute(ctx_cp,    cudaFuncAttributeMaxDynamicSharedMemorySize, SMEM_C);

    const dim3 gDD(CD / 128, CM / 128);

    gemm_cp<1, false><<<gDD, 256, SMEM_G>>>(x, wq, bq, pq, CM, CD, CD);
    gemm_cp<1, false><<<gDD, 256, SMEM_G>>>(x, wk, bk, pk, CM, CD, CD);
    gemm_cp<1, false><<<gDD, 256, SMEM_G>>>(x, wv, bv, pv, CM, CD, CD);

    scores_cp<<<dim3(CS/128, CS/128, CB*CH), 256, SMEM_S>>>();
    denom_tc<<<(unsigned)((size_t)CB*CS*CS/4/256), 256>>>();
    ctx_cp<<<dim3(CS/128, CB*CH), 256, SMEM_C>>>();

    gemm_cp<0, false><<<gDD, 256, SMEM_G>>>(pctx, wo, bo, pt0, CM, CD, CD);
    ln_kernel<<<CM, 256>>>(x, pt0, g1, be1, px1);

    gemm_cp<0, true ><<<dim3(CDFF/128, CM/128), 256, SMEM_G>>>(px1, w1, b1, pff, CM, CDFF, CD);
    gemm_cp<0, false><<<gDD, 256, SMEM_G>>>(pff, w2, b2, pt0, CM, CD, CDFF);
    ln_kernel<<<CM, 256>>>(px1, pt0, g2, be2, out);
}

// round 9
// speedup vs baseline: 5.5857x; 2.8349x over previous
#include <cuda_runtime.h>
#include <cuda_fp16.h>
#include <cstdint>

constexpr int CB  = 2;
constexpr int CS  = 2048;
constexpr int CD  = 1024;
constexpr int CH  = 16;
constexpr int CDK = 64;
constexpr int CDFF= 4096;
constexpr int CM  = CB * CS;   // 4096

// ------------------------- scratch (device globals) --------------------------
__device__ __half g_xh [(size_t)CM*CD];
__device__ __half g_wqh[(size_t)CD*CD];
__device__ __half g_wkh[(size_t)CD*CD];
__device__ __half g_wvh[(size_t)CD*CD];
__device__ __half g_woh[(size_t)CD*CD];
__device__ __half g_w1h[(size_t)CD*CDFF];
__device__ __half g_w2h[(size_t)CDFF*CD];
__device__ __half g_qh [(size_t)CB*CH*CS*CDK];
__device__ __half g_kh [(size_t)CB*CH*CS*CDK];
__device__ __half g_vh [(size_t)CB*CH*CS*CDK];
__device__ __half g_Eh [(size_t)CB*CH*CS*CS];
__device__ __half g_rdh[(size_t)CB*CS*CS];
__device__ __half g_ctxh[(size_t)CM*CD];
__device__ __half g_x1h[(size_t)CM*CD];
__device__ __half g_ffh[(size_t)CM*CDFF];
__device__ float  g_t0 [(size_t)CM*CD];
__device__ float  g_x1 [(size_t)CM*CD];

// ------------------------- helpers ------------------------------------------
__device__ __forceinline__ float fast_exp(float x) {
    const float L2E = 1.4426950408889634f;
    float t = fmaf(x, L2E, 12582912.0f);
    int   e = __float_as_int(t) - 0x4B400000;
    float r = t - 12582912.0f;
    float f = fmaf(x, L2E, -r);
    float p =            1.3333558e-3f;
    p = fmaf(p, f, 9.6181291e-3f);
    p = fmaf(p, f, 5.5504109e-2f);
    p = fmaf(p, f, 2.4022651e-1f);
    p = fmaf(p, f, 6.9314718e-1f);
    p = fmaf(p, f, 1.0f);
    return __int_as_float(__float_as_int(p) + (e << 23));
}
__device__ __forceinline__ uint32_t smem_u32(const void* p) {
    uint32_t a;
    asm("{ .reg .u64 t; cvta.to.shared.u64 t, %1; cvt.u32.u64 %0, t; }" : "=r"(a) : "l"(p));
    return a;
}
__device__ __forceinline__ void cp16(uint32_t dst, const void* src) {
    asm volatile("cp.async.cg.shared.global [%0], [%1], 16;"
                 :: "r"(dst), "l"((unsigned long long)__cvta_generic_to_global(src)));
}
#define CP_COMMIT() asm volatile("cp.async.commit_group;" ::: "memory")
#define CP_WAIT(n)  asm volatile("cp.async.wait_group %0;" :: "n"(n) : "memory")

#define LDSM4(r, a) \
    asm volatile("ldmatrix.sync.aligned.m8n8.x4.shared.b16 {%0,%1,%2,%3}, [%4];" \
        : "=r"((r)[0]), "=r"((r)[1]), "=r"((r)[2]), "=r"((r)[3]) : "r"(a))
#define LDSM4T(r, a) \
    asm volatile("ldmatrix.sync.aligned.m8n8.x4.trans.shared.b16 {%0,%1,%2,%3}, [%4];" \
        : "=r"((r)[0]), "=r"((r)[1]), "=r"((r)[2]), "=r"((r)[3]) : "r"(a))
#define MMA16(c, a, b0, b1) \
    asm volatile("mma.sync.aligned.m16n8k16.row.col.f32.f16.f16.f32 " \
        "{%0,%1,%2,%3},{%4,%5,%6,%7},{%8,%9},{%0,%1,%2,%3};" \
        : "+f"((c)[0]), "+f"((c)[1]), "+f"((c)[2]), "+f"((c)[3]) \
        : "r"((a)[0]), "r"((a)[1]), "r"((a)[2]), "r"((a)[3]), "r"(b0), "r"(b1))

__device__ __forceinline__ uint32_t hmul2u(uint32_t a, uint32_t b) {
    __half2 r = __hmul2(*(__half2*)&a, *(__half2*)&b);
    return *(uint32_t*)&r;
}

// ------------------------- f32 -> f16 convert --------------------------------
__global__ void f2h(const float* __restrict__ s, __half* __restrict__ d) {
    const size_t i8 = ((size_t)blockIdx.x * 256 + threadIdx.x) * 8;
    float4 u0 = *(const float4*)(s + i8);
    float4 u1 = *(const float4*)(s + i8 + 4);
    __half2 h0 = __floats2half2_rn(u0.x, u0.y);
    __half2 h1 = __floats2half2_rn(u0.z, u0.w);
    __half2 h2 = __floats2half2_rn(u1.x, u1.y);
    __half2 h3 = __floats2half2_rn(u1.z, u1.w);
    uint4 o;
    o.x = *(uint32_t*)&h0; o.y = *(uint32_t*)&h1;
    o.z = *(uint32_t*)&h2; o.w = *(uint32_t*)&h3;
    *(uint4*)(d + i8) = o;
}

// ======================= dense GEMM fp16 (ldmatrix + m16n8k16) ===============
// A [M,K] rm fp16, W [K,N] rm fp16. OMODE: 0 fp32 rm, 1 fp16 head-split, 2 fp16 rm.
template<int OMODE, bool RELU>
__global__ __launch_bounds__(256, 2)
void gemm_h(const __half* __restrict__ A, const __half* __restrict__ W,
            const float* __restrict__ bias, void* __restrict__ Cout,
            int M, int N, int K)
{
    constexpr int AST = 40, BST = 136;                       // halves
    constexpr int ASZ = 128 * AST, BSZ = 32 * BST, STG = ASZ + BSZ;
    extern __shared__ __half sh[];
    const uint32_t smb = smem_u32(sh);

    const int tid = threadIdx.x, wid = tid >> 5, lane = tid & 31;
    const int wm = wid >> 1, wn = wid & 1;
    const int gid = lane >> 2, tig = lane & 3;
    const int bm = blockIdx.y * 128, bn = blockIdx.x * 128;

    auto issue = [&](int kt) {
        const int st = kt & 3;
        const __half* As = A + (size_t)bm * K + kt * 32;
        const __half* Ws = W + (size_t)(kt * 32) * N + bn;
        #pragma unroll
        for (int i = 0; i < 2; i++) {
            const int c = i * 256 + tid;
            const int r = c >> 2, h8 = (c & 3) * 8;
            cp16(smb + (st * STG + r * AST + h8) * 2, As + (size_t)r * K + h8);
        }
        #pragma unroll
        for (int i = 0; i < 2; i++) {
            const int c = i * 256 + tid;
            const int kk = c >> 4, n8 = (c & 15) * 8;
            cp16(smb + (st * STG + ASZ + kk * BST + n8) * 2, Ws + (size_t)kk * N + n8);
        }
    };

    float acc[2][8][4] = {};
    const int nt = K / 32;
    issue(0); CP_COMMIT();
    issue(1); CP_COMMIT();
    issue(2); CP_COMMIT();

    for (int kt = 0; kt < nt; kt++) {
        CP_WAIT(2);
        __syncthreads();
        if (kt + 3 < nt) issue(kt + 3);
        CP_COMMIT();

        const uint32_t stA = smb + (kt & 3) * STG * 2;
        const uint32_t stB = stA + ASZ * 2;
        #pragma unroll
        for (int h16 = 0; h16 < 2; h16++) {
            const int kk16 = h16 * 16;
            uint32_t a[2][4], b[8][2];
            #pragma unroll
            for (int mi = 0; mi < 2; mi++) {
                const uint32_t ad = stA +
                    ((wm * 32 + mi * 16 + (lane & 15)) * AST + kk16 + (lane >> 4) * 8) * 2;
                LDSM4(a[mi], ad);
            }
            #pragma unroll
            for (int p = 0; p < 4; p++) {
                const int n0 = wn * 64 + p * 16;
                const uint32_t ad = stB +
                    ((kk16 + (lane & 7) + ((lane >> 3) & 1) * 8) * BST + n0 + (lane >> 4) * 8) * 2;
                uint32_t r[4];
                LDSM4T(r, ad);
                b[2*p  ][0] = r[0]; b[2*p  ][1] = r[1];
                b[2*p+1][0] = r[2]; b[2*p+1][1] = r[3];
            }
            #pragma unroll
            for (int mi = 0; mi < 2; mi++)
                #pragma unroll
                for (int ni = 0; ni < 8; ni++)
                    MMA16(acc[mi][ni], a[mi], b[ni][0], b[ni][1]);
        }
    }

    #pragma unroll
    for (int mi = 0; mi < 2; mi++) {
        #pragma unroll
        for (int ni = 0; ni < 8; ni++) {
            const int row = bm + wm * 32 + mi * 16 + gid;
            const int col = bn + wn * 64 + ni * 8 + tig * 2;
            const float2 b2 = *(const float2*)(bias + col);
            float v0 = acc[mi][ni][0] + b2.x, v1 = acc[mi][ni][1] + b2.y;
            float v2 = acc[mi][ni][2] + b2.x, v3 = acc[mi][ni][3] + b2.y;
            if (RELU) { v0 = fmaxf(v0, 0.f); v1 = fmaxf(v1, 0.f);
                        v2 = fmaxf(v2, 0.f); v3 = fmaxf(v3, 0.f); }
            if (OMODE == 0) {
                float* C = (float*)Cout;
                *(float2*)(C + (size_t)row       * N + col) = make_float2(v0, v1);
                *(float2*)(C + (size_t)(row + 8) * N + col) = make_float2(v2, v3);
            } else if (OMODE == 2) {
                __half* C = (__half*)Cout;
                *(__half2*)(C + (size_t)row       * N + col) = __floats2half2_rn(v0, v1);
                *(__half2*)(C + (size_t)(row + 8) * N + col) = __floats2half2_rn(v2, v3);
            } else {
                __half* C = (__half*)Cout;
                const int b = row >> 11, s1 = row & (CS - 1);
                const int h = col >> 6,  dk = col & 63;
                *(__half2*)(C + (((size_t)(b*CH + h))*CS + s1    )*CDK + dk) = __floats2half2_rn(v0, v1);
                *(__half2*)(C + (((size_t)(b*CH + h))*CS + s1 + 8)*CDK + dk) = __floats2half2_rn(v2, v3);
            }
        }
    }
}

// ======================= scores: E = exp((Q@K^T)/8) fp16 =====================
__global__ __launch_bounds__(256, 2)
void scores_h()
{
    constexpr int QST = 72;                 // halves per row (64 + 8 pad)
    constexpr int QSZ = 128 * QST;
    extern __shared__ __half sh[];
    const uint32_t smb = smem_u32(sh);

    const int tid = threadIdx.x, wid = tid >> 5, lane = tid & 31;
    const int wm = wid >> 1, wn = wid & 1;
    const int gid = lane >> 2, tig = lane & 3;
    const int bh = blockIdx.z;
    const int q0 = blockIdx.y * 128, k0 = blockIdx.x * 128;
    const __half* qb = g_qh + (size_t)bh * CS * CDK;
    const __half* kb = g_kh + (size_t)bh * CS * CDK;

    #pragma unroll
    for (int i = 0; i < 4; i++) {
        const int c = i * 256 + tid;
        const int r = c >> 3, h8 = (c & 7) * 8;
        cp16(smb + (r * QST + h8) * 2,             qb + (size_t)(q0 + r) * CDK + h8);
        cp16(smb + (QSZ + r * QST + h8) * 2,       kb + (size_t)(k0 + r) * CDK + h8);
    }
    CP_COMMIT();
    CP_WAIT(0);
    __syncthreads();

    float acc[2][8][4] = {};
    const uint32_t stQ = smb, stK = smb + QSZ * 2;
    #pragma unroll
    for (int h16 = 0; h16 < 4; h16++) {
        const int kk16 = h16 * 16;
        uint32_t a[2][4], b[8][2];
        #pragma unroll
        for (int mi = 0; mi < 2; mi++) {
            const uint32_t ad = stQ +
                ((wm * 32 + mi * 16 + (lane & 15)) * QST + kk16 + (lane >> 4) * 8) * 2;
            LDSM4(a[mi], ad);
        }
        #pragma unroll
        for (int p = 0; p < 4; p++) {
            const int n0 = wn * 64 + p * 16;
            const uint32_t ad = stK +
                ((n0 + (lane & 15)) * QST + kk16 + (lane >> 4) * 8) * 2;
            uint32_t r[4];
            LDSM4(r, ad);
            b[2*p  ][0] = r[0]; b[2*p  ][1] = r[2];
            b[2*p+1][0] = r[1]; b[2*p+1][1] = r[3];
        }
        #pragma unroll
        for (int mi = 0; mi < 2; mi++)
            #pragma unroll
            for (int ni = 0; ni < 8; ni++)
                MMA16(acc[mi][ni], a[mi], b[ni][0], b[ni][1]);
    }

    __half* Eb = g_Eh + (size_t)bh * CS * CS;
    #pragma unroll
    for (int mi = 0; mi < 2; mi++) {
        #pragma unroll
        for (int ni = 0; ni < 8; ni++) {
            const int q = q0 + wm * 32 + mi * 16 + gid;
            const int k = k0 + wn * 64 + ni * 8 + tig * 2;
            *(__half2*)(Eb + (size_t)q       * CS + k) =
                __floats2half2_rn(fast_exp(acc[mi][ni][0] * 0.125f),
                                  fast_exp(acc[mi][ni][1] * 0.125f));
            *(__half2*)(Eb + (size_t)(q + 8) * CS + k) =
                __floats2half2_rn(fast_exp(acc[mi][ni][2] * 0.125f),
                                  fast_exp(acc[mi][ni][3] * 0.125f));
        }
    }
}

// ======================= denom: rd = 1/sum_h E  (tensor-core head sum) =======
// CTA handles 2048 positions of one batch. E tile [16 heads][2048] in smem.
__global__ __launch_bounds__(256, 2)
void denom_h()
{
    constexpr int DST = 2056;               // halves per head row (2048 + 8)
    extern __shared__ __half sh[];
    const uint32_t smb = smem_u32(sh);

    const int tid = threadIdx.x, wid = tid >> 5, lane = tid & 31;
    const int b = blockIdx.y;
    const size_t p0 = (size_t)blockIdx.x * 2048;
    const size_t plane = (size_t)CS * CS;

    #pragma unroll
    for (int i = 0; i < 16; i++) {
        const int c = i * 256 + tid;
        const int h = c >> 8, n16 = c & 255;
        cp16(smb + (h * DST + n16 * 8) * 2,
             g_Eh + ((size_t)(b * CH + h)) * plane + p0 + n16 * 8);
    }
    CP_COMMIT();
    CP_WAIT(0);
    __syncthreads();

    const uint32_t one2 = 0x3C003C00u;      // half2(1,1)
    uint32_t a[4] = { one2, one2, one2, one2 };
    __half* rdb = g_rdh + (size_t)b * plane;

    #pragma unroll
    for (int mg = 0; mg < 16; mg++) {
        const int n0 = wid * 256 + mg * 16;
        const uint32_t ad = smb +
            (((lane & 7) + ((lane >> 3) & 1) * 8) * DST + n0 + (lane >> 4) * 8) * 2;
        uint32_t r[4];
        LDSM4T(r, ad);
        float c0[4] = {}, c1[4] = {};
        MMA16(c0, a, r[0], r[1]);
        MMA16(c1, a, r[2], r[3]);
        if (lane < 4) {
            const size_t p = p0 + n0 + lane * 2;
            *(__half2*)(rdb + p)     = __floats2half2_rn(1.0f / c0[0], 1.0f / c0[1]);
            *(__half2*)(rdb + p + 8) = __floats2half2_rn(1.0f / c1[0], 1.0f / c1[1]);
        }
    }
}

// ======================= ctx: (E*rd) @ V fp16 -> ctx fp16 ====================
__global__ __launch_bounds__(256, 2)
void ctx_h()
{
    constexpr int EST = 40, VST = 72;       // halves
    constexpr int ESZ = 128 * EST, VSZ = 32 * VST;
    constexpr int STG = 2 * ESZ + VSZ;
    extern __shared__ __half sh[];
    const uint32_t smb = smem_u32(sh);

    const int tid = threadIdx.x, wid = tid >> 5, lane = tid & 31;
    const int wm = wid >> 1, wn = wid & 1;
    const int gid = lane >> 2, tig = lane & 3;
    const int bh = blockIdx.y;
    const int b = bh >> 4, h = bh & 15;
    const int q0 = blockIdx.x * 128;
    const size_t plane = (size_t)CS * CS;
    const __half* eb = g_Eh  + (size_t)bh * plane;
    const __half* rb = g_rdh + (size_t)b  * plane;
    const __half* vb = g_vh  + (size_t)bh * CS * CDK;

    auto issue = [&](int kt) {
        const int st = kt & 3;
        const int kb = kt * 32;
        #pragma unroll
        for (int i = 0; i < 2; i++) {
            const int c = i * 256 + tid;
            const int r = c >> 2, h8 = (c & 3) * 8;
            cp16(smb + (st * STG + r * EST + h8) * 2,       eb + (size_t)(q0 + r) * CS + kb + h8);
            cp16(smb + (st * STG + ESZ + r * EST + h8) * 2, rb + (size_t)(q0 + r) * CS + kb + h8);
        }
        const int kk = tid >> 3, n8 = (tid & 7) * 8;
        cp16(smb + (st * STG + 2 * ESZ + kk * VST + n8) * 2, vb + (size_t)(kb + kk) * CDK + n8);
    };

    float acc[2][4][4] = {};
    const int nt = CS / 32;
    issue(0); CP_COMMIT();
    issue(1); CP_COMMIT();
    issue(2); CP_COMMIT();

    for (int kt = 0; kt < nt; kt++) {
        CP_WAIT(2);
        __syncthreads();
        if (kt + 3 < nt) issue(kt + 3);
        CP_COMMIT();

        const uint32_t stE = smb + (kt & 3) * STG * 2;
        const uint32_t stR = stE + ESZ * 2;
        const uint32_t stV = stR + ESZ * 2;
        #pragma unroll
        for (int h16 = 0; h16 < 2; h16++) {
            const int kk16 = h16 * 16;
            uint32_t ae[2][4], ar[2][4], a[2][4], bv[4][2];
            #pragma unroll
            for (int mi = 0; mi < 2; mi++) {
                const uint32_t off =
                    ((wm * 32 + mi * 16 + (lane & 15)) * EST + kk16 + (lane >> 4) * 8) * 2;
                LDSM4(ae[mi], stE + off);
                LDSM4(ar[mi], stR + off);
                #pragma unroll
                for (int j = 0; j < 4; j++) a[mi][j] = hmul2u(ae[mi][j], ar[mi][j]);
            }
            #pragma unroll
            for (int p = 0; p < 2; p++) {
                const int n0 = wn * 32 + p * 16;
                const uint32_t ad = stV +
                    ((kk16 + (lane & 7) + ((lane >> 3) & 1) * 8) * VST + n0 + (lane >> 4) * 8) * 2;
                uint32_t r[4];
                LDSM4T(r, ad);
                bv[2*p  ][0] = r[0]; bv[2*p  ][1] = r[1];
                bv[2*p+1][0] = r[2]; bv[2*p+1][1] = r[3];
            }
            #pragma unroll
            for (int mi = 0; mi < 2; mi++)
                #pragma unroll
                for (int ni = 0; ni < 4; ni++)
                    MMA16(acc[mi][ni], a[mi], bv[ni][0], bv[ni][1]);
        }
    }

    #pragma unroll
    for (int mi = 0; mi < 2; mi++) {
        #pragma unroll
        for (int ni = 0; ni < 4; ni++) {
            const int q = q0 + wm * 32 + mi * 16 + gid;
            const int n = wn * 32 + ni * 8 + tig * 2;
            __half* p0p = g_ctxh + (((size_t)(b * CS + q    )) * CH + h) * CDK + n;
            __half* p1p = g_ctxh + (((size_t)(b * CS + q + 8)) * CH + h) * CDK + n;
            *(__half2*)p0p = __floats2half2_rn(acc[mi][ni][0], acc[mi][ni][1]);
            *(__half2*)p1p = __floats2half2_rn(acc[mi][ni][2], acc[mi][ni][3]);
        }
    }
}

// ------------------------- residual + LayerNorm ------------------------------
__global__ void ln_kernel(const float* __restrict__ A, const float* __restrict__ Bp,
                          const float* __restrict__ g, const float* __restrict__ be,
                          float* __restrict__ out, __half* __restrict__ outh)
{
    const int row = blockIdx.x;
    const int tid = threadIdx.x;
    const int i0 = tid << 2;
    float4 a  = *(const float4*)(A  + (size_t)row*CD + i0);
    float4 bb = *(const float4*)(Bp + (size_t)row*CD + i0);
    const float v0 = a.x + bb.x, v1 = a.y + bb.y, v2 = a.z + bb.z, v3 = a.w + bb.w;
    float s  = v0 + v1 + v2 + v3;
    float ss = v0*v0 + v1*v1 + v2*v2 + v3*v3;
    #pragma unroll
    for (int o = 16; o; o >>= 1) {
        s  += __shfl_xor_sync(0xffffffffu, s,  o);
        ss += __shfl_xor_sync(0xffffffffu, ss, o);
    }
    __shared__ float sh1[8], sh2[8];
    if ((tid & 31) == 0) { sh1[tid >> 5] = s; sh2[tid >> 5] = ss; }
    __syncthreads();
    s = 0.f; ss = 0.f;
    #pragma unroll
    for (int w = 0; w < 8; w++) { s += sh1[w]; ss += sh2[w]; }
    const float mean = s * (1.0f / CD);
    const float var  = ss * (1.0f / CD) - mean * mean;
    const float rstd = rsqrtf(var + 1e-5f);
    float4 gg = *(const float4*)(g  + i0);
    float4 bt = *(const float4*)(be + i0);
    float4 o4;
    o4.x = (v0 - mean) * rstd * gg.x + bt.x;
    o4.y = (v1 - mean) * rstd * gg.y + bt.y;
    o4.z = (v2 - mean) * rstd * gg.z + bt.z;
    o4.w = (v3 - mean) * rstd * gg.w + bt.w;
    *(float4*)(out + (size_t)row*CD + i0) = o4;
    if (outh) {
        __half2 h0 = __floats2half2_rn(o4.x, o4.y);
        __half2 h1 = __floats2half2_rn(o4.z, o4.w);
        uint2 u; u.x = *(uint32_t*)&h0; u.y = *(uint32_t*)&h1;
        *(uint2*)(outh + (size_t)row*CD + i0) = u;
    }
}

// ------------------------- launch -------------------------------------------
extern "C" void kernel_launch(void* const* d_in, const int* in_sizes, int n_in,
                              void* d_out, int out_size)
{
    (void)in_sizes; (void)n_in; (void)out_size;
    const float* x   = (const float*)d_in[0];
    const float* wq  = (const float*)d_in[1];
    const float* bq  = (const float*)d_in[2];
    const float* wk  = (const float*)d_in[3];
    const float* bk  = (const float*)d_in[4];
    const float* wv  = (const float*)d_in[5];
    const float* bv  = (const float*)d_in[6];
    const float* wo  = (const float*)d_in[7];
    const float* bo  = (const float*)d_in[8];
    const float* g1  = (const float*)d_in[9];
    const float* be1 = (const float*)d_in[10];
    const float* w1  = (const float*)d_in[11];
    const float* b1  = (const float*)d_in[12];
    const float* w2  = (const float*)d_in[13];
    const float* b2  = (const float*)d_in[14];
    const float* g2  = (const float*)d_in[15];
    const float* be2 = (const float*)d_in[16];
    float* out = (float*)d_out;

    __half *pxh, *pwqh, *pwkh, *pwvh, *pwoh, *pw1h, *pw2h;
    __half *pqh, *pkh, *pvh, *pctxh, *px1h, *pffh;
    float *pt0, *px1;
    cudaGetSymbolAddress((void**)&pxh,  g_xh);
    cudaGetSymbolAddress((void**)&pwqh, g_wqh);
    cudaGetSymbolAddress((void**)&pwkh, g_wkh);
    cudaGetSymbolAddress((void**)&pwvh, g_wvh);
    cudaGetSymbolAddress((void**)&pwoh, g_woh);
    cudaGetSymbolAddress((void**)&pw1h, g_w1h);
    cudaGetSymbolAddress((void**)&pw2h, g_w2h);
    cudaGetSymbolAddress((void**)&pqh,  g_qh);
    cudaGetSymbolAddress((void**)&pkh,  g_kh);
    cudaGetSymbolAddress((void**)&pvh,  g_vh);
    cudaGetSymbolAddress((void**)&pctxh,g_ctxh);
    cudaGetSymbolAddress((void**)&px1h, g_x1h);
    cudaGetSymbolAddress((void**)&pffh, g_ffh);
    cudaGetSymbolAddress((void**)&pt0,  g_t0);
    cudaGetSymbolAddress((void**)&px1,  g_x1);

    const int SMEM_G = (128*40 + 32*136) * 4 * 2;        // 4 stages * STG halves * 2B
    const int SMEM_S = 2 * 128*72 * 2;                   // 36864
    const int SMEM_D = 16 * 2056 * 2;                    // 65792
    const int SMEM_C = 4 * (2*128*40 + 32*72) * 2;       // 100352
    cudaFuncSetAttribute(gemm_h<0,false>, cudaFuncAttributeMaxDynamicSharedMemorySize, SMEM_G);
    cudaFuncSetAttribute(gemm_h<1,false>, cudaFuncAttributeMaxDynamicSharedMemorySize, SMEM_G);
    cudaFuncSetAttribute(gemm_h<2,true >, cudaFuncAttributeMaxDynamicSharedMemorySize, SMEM_G);
    cudaFuncSetAttribute(scores_h, cudaFuncAttributeMaxDynamicSharedMemorySize, SMEM_S);
    cudaFuncSetAttribute(denom_h,  cudaFuncAttributeMaxDynamicSharedMemorySize, SMEM_D);
    cudaFuncSetAttribute(ctx_h,    cudaFuncAttributeMaxDynamicSharedMemorySize, SMEM_C);

    // convert inputs/weights to fp16
    f2h<<<(unsigned)((size_t)CM*CD/2048), 256>>>(x,  pxh);
    f2h<<<(unsigned)((size_t)CD*CD/2048), 256>>>(wq, pwqh);
    f2h<<<(unsigned)((size_t)CD*CD/2048), 256>>>(wk, pwkh);
    f2h<<<(unsigned)((size_t)CD*CD/2048), 256>>>(wv, pwvh);
    f2h<<<(unsigned)((size_t)CD*CD/2048), 256>>>(wo, pwoh);
    f2h<<<(unsigned)((size_t)CD*CDFF/2048), 256>>>(w1, pw1h);
    f2h<<<(unsigned)((size_t)CDFF*CD/2048), 256>>>(w2, pw2h);

    const dim3 gDD(CD / 128, CM / 128);

    gemm_h<1, false><<<gDD, 256, SMEM_G>>>(pxh, pwqh, bq, pqh, CM, CD, CD);
    gemm_h<1, false><<<gDD, 256, SMEM_G>>>(pxh, pwkh, bk, pkh, CM, CD, CD);
    gemm_h<1, false><<<gDD, 256, SMEM_G>>>(pxh, pwvh, bv, pvh, CM, CD, CD);

    scores_h<<<dim3(CS/128, CS/128, CB*CH), 256, SMEM_S>>>();
    denom_h<<<dim3((unsigned)((size_t)CS*CS/2048), CB), 256, SMEM_D>>>();
    ctx_h<<<dim3(CS/128, CB*CH), 256, SMEM_C>>>();

    gemm_h<0, false><<<gDD, 256, SMEM_G>>>(pctxh, pwoh, bo, pt0, CM, CD, CD);
    ln_kernel<<<CM, 256>>>(x, pt0, g1, be1, px1, px1h);

    gemm_h<2, true ><<<dim3(CDFF/128, CM/128), 256, SMEM_G>>>(px1h, pw1h, b1, pffh, CM, CDFF, CD);
    gemm_h<0, false><<<gDD, 256, SMEM_G>>>(pffh, pw2h, b2, pt0, CM, CD, CDFF);
    ln_kernel<<<CM, 256>>>(px1, pt0, g2, be2, out, nullptr);
}

// round 11
// speedup vs baseline: 6.1714x; 1.1049x over previous
#include <cuda_runtime.h>
#include <cuda_fp16.h>
#include <cstdint>

constexpr int CB  = 2;
constexpr int CS  = 2048;
constexpr int CD  = 1024;
constexpr int CH  = 16;
constexpr int CDK = 64;
constexpr int CDFF= 4096;
constexpr int CM  = CB * CS;   // 4096

// ------------------------- scratch (device globals) --------------------------
__device__ __half g_xh [(size_t)CM*CD];
__device__ __half g_wqh[(size_t)CD*CD];
__device__ __half g_wkh[(size_t)CD*CD];
__device__ __half g_wvh[(size_t)CD*CD];
__device__ __half g_woh[(size_t)CD*CD];
__device__ __half g_w1h[(size_t)CD*CDFF];
__device__ __half g_w2h[(size_t)CDFF*CD];
__device__ __half g_qh [(size_t)CB*CH*CS*CDK];
__device__ __half g_kh [(size_t)CB*CH*CS*CDK];
__device__ __half g_vh [(size_t)CB*CH*CS*CDK];
__device__ __half g_Eh [(size_t)CB*CH*CS*CS];
__device__ __half g_rdh[(size_t)CB*CS*CS];
__device__ __half g_ctxh[(size_t)CM*CD];
__device__ __half g_x1h[(size_t)CM*CD];
__device__ __half g_ffh[(size_t)CM*CDFF];
__device__ float  g_t0 [(size_t)CM*CD];
__device__ float  g_x1 [(size_t)CM*CD];

// ------------------------- helpers ------------------------------------------
__device__ __forceinline__ float fast_exp(float x) {
    const float L2E = 1.4426950408889634f;
    float t = fmaf(x, L2E, 12582912.0f);
    int   e = __float_as_int(t) - 0x4B400000;
    float r = t - 12582912.0f;
    float f = fmaf(x, L2E, -r);
    float p =            1.3333558e-3f;
    p = fmaf(p, f, 9.6181291e-3f);
    p = fmaf(p, f, 5.5504109e-2f);
    p = fmaf(p, f, 2.4022651e-1f);
    p = fmaf(p, f, 6.9314718e-1f);
    p = fmaf(p, f, 1.0f);
    return __int_as_float(__float_as_int(p) + (e << 23));
}
__device__ __forceinline__ uint32_t smem_u32(const void* p) {
    uint32_t a;
    asm("{ .reg .u64 t; cvta.to.shared.u64 t, %1; cvt.u32.u64 %0, t; }" : "=r"(a) : "l"(p));
    return a;
}
__device__ __forceinline__ void cp16(uint32_t dst, const void* src) {
    asm volatile("cp.async.cg.shared.global [%0], [%1], 16;"
                 :: "r"(dst), "l"((unsigned long long)__cvta_generic_to_global(src)));
}
#define CP_COMMIT() asm volatile("cp.async.commit_group;" ::: "memory")
#define CP_WAIT(n)  asm volatile("cp.async.wait_group %0;" :: "n"(n) : "memory")

#define LDSM4(r, a) \
    asm volatile("ldmatrix.sync.aligned.m8n8.x4.shared.b16 {%0,%1,%2,%3}, [%4];" \
        : "=r"((r)[0]), "=r"((r)[1]), "=r"((r)[2]), "=r"((r)[3]) : "r"(a))
#define LDSM4T(r, a) \
    asm volatile("ldmatrix.sync.aligned.m8n8.x4.trans.shared.b16 {%0,%1,%2,%3}, [%4];" \
        : "=r"((r)[0]), "=r"((r)[1]), "=r"((r)[2]), "=r"((r)[3]) : "r"(a))
#define MMA16(c, a, b0, b1) \
    asm volatile("mma.sync.aligned.m16n8k16.row.col.f32.f16.f16.f32 " \
        "{%0,%1,%2,%3},{%4,%5,%6,%7},{%8,%9},{%0,%1,%2,%3};" \
        : "+f"((c)[0]), "+f"((c)[1]), "+f"((c)[2]), "+f"((c)[3]) \
        : "r"((a)[0]), "r"((a)[1]), "r"((a)[2]), "r"((a)[3]), "r"(b0), "r"(b1))

__device__ __forceinline__ uint32_t hmul2u(uint32_t a, uint32_t b) {
    __half2 r = __hmul2(*(__half2*)&a, *(__half2*)&b);
    return *(uint32_t*)&r;
}

// ------------------------- fused f32 -> f16 convert (all tensors) ------------
__global__ void f2h_all(const float* __restrict__ x,
                        const float* __restrict__ wq, const float* __restrict__ wk,
                        const float* __restrict__ wv, const float* __restrict__ wo,
                        const float* __restrict__ w1, const float* __restrict__ w2,
                        __half* __restrict__ xh,
                        __half* __restrict__ wqh, __half* __restrict__ wkh,
                        __half* __restrict__ wvh, __half* __restrict__ woh,
                        __half* __restrict__ w1h, __half* __restrict__ w2h)
{
    const size_t e8 = ((size_t)blockIdx.x * 256 + threadIdx.x) * 8;
    const float* s; __half* d; size_t off;
    if      (e8 <  4194304) { s = x;  d = xh;  off = e8; }
    else if (e8 <  5242880) { s = wq; d = wqh; off = e8 -  4194304; }
    else if (e8 <  6291456) { s = wk; d = wkh; off = e8 -  5242880; }
    else if (e8 <  7340032) { s = wv; d = wvh; off = e8 -  6291456; }
    else if (e8 <  8388608) { s = wo; d = woh; off = e8 -  7340032; }
    else if (e8 < 12582912) { s = w1; d = w1h; off = e8 -  8388608; }
    else                    { s = w2; d = w2h; off = e8 - 12582912; }
    float4 u0 = *(const float4*)(s + off);
    float4 u1 = *(const float4*)(s + off + 4);
    __half2 h0 = __floats2half2_rn(u0.x, u0.y);
    __half2 h1 = __floats2half2_rn(u0.z, u0.w);
    __half2 h2 = __floats2half2_rn(u1.x, u1.y);
    __half2 h3 = __floats2half2_rn(u1.z, u1.w);
    uint4 o;
    o.x = *(uint32_t*)&h0; o.y = *(uint32_t*)&h1;
    o.z = *(uint32_t*)&h2; o.w = *(uint32_t*)&h3;
    *(uint4*)(d + off) = o;
}

// ======================= dense GEMM fp16 (ldmatrix + m16n8k16) ===============
template<int OMODE, bool RELU>
__global__ __launch_bounds__(256, 2)
void gemm_h(const __half* __restrict__ A, const __half* __restrict__ W,
            const float* __restrict__ bias, void* __restrict__ Cout,
            int M, int N, int K)
{
    constexpr int AST = 40, BST = 136;
    constexpr int ASZ = 128 * AST, BSZ = 32 * BST, STG = ASZ + BSZ;
    extern __shared__ __half sh[];
    const uint32_t smb = smem_u32(sh);

    const int tid = threadIdx.x, wid = tid >> 5, lane = tid & 31;
    const int wm = wid >> 1, wn = wid & 1;
    const int gid = lane >> 2, tig = lane & 3;
    const int bm = blockIdx.y * 128, bn = blockIdx.x * 128;

    auto issue = [&](int kt) {
        const int st = kt & 3;
        const __half* As = A + (size_t)bm * K + kt * 32;
        const __half* Ws = W + (size_t)(kt * 32) * N + bn;
        #pragma unroll
        for (int i = 0; i < 2; i++) {
            const int c = i * 256 + tid;
            const int r = c >> 2, h8 = (c & 3) * 8;
            cp16(smb + (st * STG + r * AST + h8) * 2, As + (size_t)r * K + h8);
        }
        #pragma unroll
        for (int i = 0; i < 2; i++) {
            const int c = i * 256 + tid;
            const int kk = c >> 4, n8 = (c & 15) * 8;
            cp16(smb + (st * STG + ASZ + kk * BST + n8) * 2, Ws + (size_t)kk * N + n8);
        }
    };

    float acc[2][8][4] = {};
    const int nt = K / 32;
    issue(0); CP_COMMIT();
    issue(1); CP_COMMIT();
    issue(2); CP_COMMIT();

    for (int kt = 0; kt < nt; kt++) {
        CP_WAIT(2);
        __syncthreads();
        if (kt + 3 < nt) issue(kt + 3);
        CP_COMMIT();

        const uint32_t stA = smb + (kt & 3) * STG * 2;
        const uint32_t stB = stA + ASZ * 2;
        #pragma unroll
        for (int h16 = 0; h16 < 2; h16++) {
            const int kk16 = h16 * 16;
            uint32_t a[2][4], b[8][2];
            #pragma unroll
            for (int mi = 0; mi < 2; mi++) {
                const uint32_t ad = stA +
                    ((wm * 32 + mi * 16 + (lane & 15)) * AST + kk16 + (lane >> 4) * 8) * 2;
                LDSM4(a[mi], ad);
            }
            #pragma unroll
            for (int p = 0; p < 4; p++) {
                const int n0 = wn * 64 + p * 16;
                const uint32_t ad = stB +
                    ((kk16 + (lane & 7) + ((lane >> 3) & 1) * 8) * BST + n0 + (lane >> 4) * 8) * 2;
                uint32_t r[4];
                LDSM4T(r, ad);
                b[2*p  ][0] = r[0]; b[2*p  ][1] = r[1];
                b[2*p+1][0] = r[2]; b[2*p+1][1] = r[3];
            }
            #pragma unroll
            for (int mi = 0; mi < 2; mi++)
                #pragma unroll
                for (int ni = 0; ni < 8; ni++)
                    MMA16(acc[mi][ni], a[mi], b[ni][0], b[ni][1]);
        }
    }

    #pragma unroll
    for (int mi = 0; mi < 2; mi++) {
        #pragma unroll
        for (int ni = 0; ni < 8; ni++) {
            const int row = bm + wm * 32 + mi * 16 + gid;
            const int col = bn + wn * 64 + ni * 8 + tig * 2;
            const float2 b2 = *(const float2*)(bias + col);
            float v0 = acc[mi][ni][0] + b2.x, v1 = acc[mi][ni][1] + b2.y;
            float v2 = acc[mi][ni][2] + b2.x, v3 = acc[mi][ni][3] + b2.y;
            if (RELU) { v0 = fmaxf(v0, 0.f); v1 = fmaxf(v1, 0.f);
                        v2 = fmaxf(v2, 0.f); v3 = fmaxf(v3, 0.f); }
            if (OMODE == 0) {
                float* C = (float*)Cout;
                *(float2*)(C + (size_t)row       * N + col) = make_float2(v0, v1);
                *(float2*)(C + (size_t)(row + 8) * N + col) = make_float2(v2, v3);
            } else if (OMODE == 2) {
                __half* C = (__half*)Cout;
                *(__half2*)(C + (size_t)row       * N + col) = __floats2half2_rn(v0, v1);
                *(__half2*)(C + (size_t)(row + 8) * N + col) = __floats2half2_rn(v2, v3);
            } else {
                __half* C = (__half*)Cout;
                const int b = row >> 11, s1 = row & (CS - 1);
                const int h = col >> 6,  dk = col & 63;
                *(__half2*)(C + (((size_t)(b*CH + h))*CS + s1    )*CDK + dk) = __floats2half2_rn(v0, v1);
                *(__half2*)(C + (((size_t)(b*CH + h))*CS + s1 + 8)*CDK + dk) = __floats2half2_rn(v2, v3);
            }
        }
    }
}

// ======================= scores + denom fused ================================
// One CTA: (q0, k0) tile of 128x64 for ALL 16 heads of batch b. Loops heads
// with double-buffered cp.async; accumulates sum_h exp in registers; writes
// E per head and rd at the end. Eliminates the separate denom kernel.
__global__ __launch_bounds__(256, 2)
void scoresum_h()
{
    constexpr int QST = 72;                     // halves per row
    constexpr int QSZ = 128 * QST, KSZ = 64 * QST, STG = QSZ + KSZ;
    extern __shared__ __half sh[];
    const uint32_t smb = smem_u32(sh);

    const int tid = threadIdx.x, wid = tid >> 5, lane = tid & 31;
    const int wm = wid >> 1, wn = wid & 1;       // 4 m-warps x 2 n-warps
    const int gid = lane >> 2, tig = lane & 3;
    const int b = blockIdx.z;
    const int q0 = blockIdx.y * 128, k0 = blockIdx.x * 64;
    const size_t plane = (size_t)CS * CS;

    auto issue = [&](int h) {
        const int st = h & 1;
        const __half* qb = g_qh + ((size_t)(b * CH + h)) * CS * CDK + (size_t)q0 * CDK;
        const __half* kb = g_kh + ((size_t)(b * CH + h)) * CS * CDK + (size_t)k0 * CDK;
        #pragma unroll
        for (int i = 0; i < 4; i++) {
            const int c = i * 256 + tid;
            const int r = c >> 3, h8 = (c & 7) * 8;
            cp16(smb + (st * STG + r * QST + h8) * 2, qb + (size_t)r * CDK + h8);
        }
        #pragma unroll
        for (int i = 0; i < 2; i++) {
            const int c = i * 256 + tid;
            const int r = c >> 3, h8 = (c & 7) * 8;
            cp16(smb + (st * STG + QSZ + r * QST + h8) * 2, kb + (size_t)r * CDK + h8);
        }
    };

    float sum[2][4][4] = {};
    issue(0); CP_COMMIT();

    for (int h = 0; h < CH; h++) {
        if (h + 1 < CH) { issue(h + 1); CP_COMMIT(); CP_WAIT(1); }
        else            { CP_WAIT(0); }
        __syncthreads();

        const uint32_t stQ = smb + (h & 1) * STG * 2;
        const uint32_t stK = stQ + QSZ * 2;

        float acc[2][4][4] = {};
        #pragma unroll
        for (int h16 = 0; h16 < 4; h16++) {
            const int kk16 = h16 * 16;
            uint32_t a[2][4], bfr[4][2];
            #pragma unroll
            for (int mi = 0; mi < 2; mi++) {
                const uint32_t ad = stQ +
                    ((wm * 32 + mi * 16 + (lane & 15)) * QST + kk16 + (lane >> 4) * 8) * 2;
                LDSM4(a[mi], ad);
            }
            #pragma unroll
            for (int p = 0; p < 2; p++) {
                const int n0 = wn * 32 + p * 16;
                const uint32_t ad = stK +
                    ((n0 + (lane & 15)) * QST + kk16 + (lane >> 4) * 8) * 2;
                uint32_t r[4];
                LDSM4(r, ad);
                bfr[2*p  ][0] = r[0]; bfr[2*p  ][1] = r[2];
                bfr[2*p+1][0] = r[1]; bfr[2*p+1][1] = r[3];
            }
            #pragma unroll
            for (int mi = 0; mi < 2; mi++)
                #pragma unroll
                for (int ni = 0; ni < 4; ni++)
                    MMA16(acc[mi][ni], a[mi], bfr[ni][0], bfr[ni][1]);
        }

        __half* Eb = g_Eh + ((size_t)(b * CH + h)) * plane;
        #pragma unroll
        for (int mi = 0; mi < 2; mi++) {
            #pragma unroll
            for (int ni = 0; ni < 4; ni++) {
                const int q = q0 + wm * 32 + mi * 16 + gid;
                const int k = k0 + wn * 32 + ni * 8 + tig * 2;
                float e0 = fast_exp(acc[mi][ni][0] * 0.125f);
                float e1 = fast_exp(acc[mi][ni][1] * 0.125f);
                float e2 = fast_exp(acc[mi][ni][2] * 0.125f);
                float e3 = fast_exp(acc[mi][ni][3] * 0.125f);
                sum[mi][ni][0] += e0; sum[mi][ni][1] += e1;
                sum[mi][ni][2] += e2; sum[mi][ni][3] += e3;
                *(__half2*)(Eb + (size_t)q       * CS + k) = __floats2half2_rn(e0, e1);
                *(__half2*)(Eb + (size_t)(q + 8) * CS + k) = __floats2half2_rn(e2, e3);
            }
        }
        __syncthreads();
    }

    __half* rdb = g_rdh + (size_t)b * plane;
    #pragma unroll
    for (int mi = 0; mi < 2; mi++) {
        #pragma unroll
        for (int ni = 0; ni < 4; ni++) {
            const int q = q0 + wm * 32 + mi * 16 + gid;
            const int k = k0 + wn * 32 + ni * 8 + tig * 2;
            *(__half2*)(rdb + (size_t)q       * CS + k) =
                __floats2half2_rn(1.0f / sum[mi][ni][0], 1.0f / sum[mi][ni][1]);
            *(__half2*)(rdb + (size_t)(q + 8) * CS + k) =
                __floats2half2_rn(1.0f / sum[mi][ni][2], 1.0f / sum[mi][ni][3]);
        }
    }
}

// ======================= ctx: (E*rd) @ V fp16 -> ctx fp16 ====================
__global__ __launch_bounds__(256, 2)
void ctx_h()
{
    constexpr int EST = 40, VST = 72;
    constexpr int ESZ = 128 * EST, VSZ = 32 * VST;
    constexpr int STG = 2 * ESZ + VSZ;
    extern __shared__ __half sh[];
    const uint32_t smb = smem_u32(sh);

    const int tid = threadIdx.x, wid = tid >> 5, lane = tid & 31;
    const int wm = wid >> 1, wn = wid & 1;
    const int gid = lane >> 2, tig = lane & 3;
    const int bh = blockIdx.y;
    const int b = bh >> 4, h = bh & 15;
    const int q0 = blockIdx.x * 128;
    const size_t plane = (size_t)CS * CS;
    const __half* eb = g_Eh  + (size_t)bh * plane;
    const __half* rb = g_rdh + (size_t)b  * plane;
    const __half* vb = g_vh  + (size_t)bh * CS * CDK;

    auto issue = [&](int kt) {
        const int st = kt & 3;
        const int kb = kt * 32;
        #pragma unroll
        for (int i = 0; i < 2; i++) {
            const int c = i * 256 + tid;
            const int r = c >> 2, h8 = (c & 3) * 8;
            cp16(smb + (st * STG + r * EST + h8) * 2,       eb + (size_t)(q0 + r) * CS + kb + h8);
            cp16(smb + (st * STG + ESZ + r * EST + h8) * 2, rb + (size_t)(q0 + r) * CS + kb + h8);
        }
        const int kk = tid >> 3, n8 = (tid & 7) * 8;
        cp16(smb + (st * STG + 2 * ESZ + kk * VST + n8) * 2, vb + (size_t)(kb + kk) * CDK + n8);
    };

    float acc[2][4][4] = {};
    const int nt = CS / 32;
    issue(0); CP_COMMIT();
    issue(1); CP_COMMIT();
    issue(2); CP_COMMIT();

    for (int kt = 0; kt < nt; kt++) {
        CP_WAIT(2);
        __syncthreads();
        if (kt + 3 < nt) issue(kt + 3);
        CP_COMMIT();

        const uint32_t stE = smb + (kt & 3) * STG * 2;
        const uint32_t stR = stE + ESZ * 2;
        const uint32_t stV = stR + ESZ * 2;
        #pragma unroll
        for (int h16 = 0; h16 < 2; h16++) {
            const int kk16 = h16 * 16;
            uint32_t ae[2][4], ar[2][4], a[2][4], bv[4][2];
            #pragma unroll
            for (int mi = 0; mi < 2; mi++) {
                const uint32_t off =
                    ((wm * 32 + mi * 16 + (lane & 15)) * EST + kk16 + (lane >> 4) * 8) * 2;
                LDSM4(ae[mi], stE + off);
                LDSM4(ar[mi], stR + off);
                #pragma unroll
                for (int j = 0; j < 4; j++) a[mi][j] = hmul2u(ae[mi][j], ar[mi][j]);
            }
            #pragma unroll
            for (int p = 0; p < 2; p++) {
                const int n0 = wn * 32 + p * 16;
                const uint32_t ad = stV +
                    ((kk16 + (lane & 7) + ((lane >> 3) & 1) * 8) * VST + n0 + (lane >> 4) * 8) * 2;
                uint32_t r[4];
                LDSM4T(r, ad);
                bv[2*p  ][0] = r[0]; bv[2*p  ][1] = r[1];
                bv[2*p+1][0] = r[2]; bv[2*p+1][1] = r[3];
            }
            #pragma unroll
            for (int mi = 0; mi < 2; mi++)
                #pragma unroll
                for (int ni = 0; ni < 4; ni++)
                    MMA16(acc[mi][ni], a[mi], bv[ni][0], bv[ni][1]);
        }
    }

    #pragma unroll
    for (int mi = 0; mi < 2; mi++) {
        #pragma unroll
        for (int ni = 0; ni < 4; ni++) {
            const int q = q0 + wm * 32 + mi * 16 + gid;
            const int n = wn * 32 + ni * 8 + tig * 2;
            __half* p0p = g_ctxh + (((size_t)(b * CS + q    )) * CH + h) * CDK + n;
            __half* p1p = g_ctxh + (((size_t)(b * CS + q + 8)) * CH + h) * CDK + n;
            *(__half2*)p0p = __floats2half2_rn(acc[mi][ni][0], acc[mi][ni][1]);
            *(__half2*)p1p = __floats2half2_rn(acc[mi][ni][2], acc[mi][ni][3]);
        }
    }
}

// ------------------------- residual + LayerNorm ------------------------------
__global__ void ln_kernel(const float* __restrict__ A, const float* __restrict__ Bp,
                          const float* __restrict__ g, const float* __restrict__ be,
                          float* __restrict__ out, __half* __restrict__ outh)
{
    const int row = blockIdx.x;
    const int tid = threadIdx.x;
    const int i0 = tid << 2;
    float4 a  = *(const float4*)(A  + (size_t)row*CD + i0);
    float4 bb = *(const float4*)(Bp + (size_t)row*CD + i0);
    const float v0 = a.x + bb.x, v1 = a.y + bb.y, v2 = a.z + bb.z, v3 = a.w + bb.w;
    float s  = v0 + v1 + v2 + v3;
    float ss = v0*v0 + v1*v1 + v2*v2 + v3*v3;
    #pragma unroll
    for (int o = 16; o; o >>= 1) {
        s  += __shfl_xor_sync(0xffffffffu, s,  o);
        ss += __shfl_xor_sync(0xffffffffu, ss, o);
    }
    __shared__ float sh1[8], sh2[8];
    if ((tid & 31) == 0) { sh1[tid >> 5] = s; sh2[tid >> 5] = ss; }
    __syncthreads();
    s = 0.f; ss = 0.f;
    #pragma unroll
    for (int w = 0; w < 8; w++) { s += sh1[w]; ss += sh2[w]; }
    const float mean = s * (1.0f / CD);
    const float var  = ss * (1.0f / CD) - mean * mean;
    const float rstd = rsqrtf(var + 1e-5f);
    float4 gg = *(const float4*)(g  + i0);
    float4 bt = *(const float4*)(be + i0);
    float4 o4;
    o4.x = (v0 - mean) * rstd * gg.x + bt.x;
    o4.y = (v1 - mean) * rstd * gg.y + bt.y;
    o4.z = (v2 - mean) * rstd * gg.z + bt.z;
    o4.w = (v3 - mean) * rstd * gg.w + bt.w;
    *(float4*)(out + (size_t)row*CD + i0) = o4;
    if (outh) {
        __half2 h0 = __floats2half2_rn(o4.x, o4.y);
        __half2 h1 = __floats2half2_rn(o4.z, o4.w);
        uint2 u; u.x = *(uint32_t*)&h0; u.y = *(uint32_t*)&h1;
        *(uint2*)(outh + (size_t)row*CD + i0) = u;
    }
}

// ------------------------- launch -------------------------------------------
extern "C" void kernel_launch(void* const* d_in, const int* in_sizes, int n_in,
                              void* d_out, int out_size)
{
    (void)in_sizes; (void)n_in; (void)out_size;
    const float* x   = (const float*)d_in[0];
    const float* wq  = (const float*)d_in[1];
    const float* bq  = (const float*)d_in[2];
    const float* wk  = (const float*)d_in[3];
    const float* bk  = (const float*)d_in[4];
    const float* wv  = (const float*)d_in[5];
    const float* bv  = (const float*)d_in[6];
    const float* wo  = (const float*)d_in[7];
    const float* bo  = (const float*)d_in[8];
    const float* g1  = (const float*)d_in[9];
    const float* be1 = (const float*)d_in[10];
    const float* w1  = (const float*)d_in[11];
    const float* b1  = (const float*)d_in[12];
    const float* w2  = (const float*)d_in[13];
    const float* b2  = (const float*)d_in[14];
    const float* g2  = (const float*)d_in[15];
    const float* be2 = (const float*)d_in[16];
    float* out = (float*)d_out;

    __half *pxh, *pwqh, *pwkh, *pwvh, *pwoh, *pw1h, *pw2h;
    __half *pqh, *pkh, *pvh, *pctxh, *px1h, *pffh;
    float *pt0, *px1;
    cudaGetSymbolAddress((void**)&pxh,  g_xh);
    cudaGetSymbolAddress((void**)&pwqh, g_wqh);
    cudaGetSymbolAddress((void**)&pwkh, g_wkh);
    cudaGetSymbolAddress((void**)&pwvh, g_wvh);
    cudaGetSymbolAddress((void**)&pwoh, g_woh);
    cudaGetSymbolAddress((void**)&pw1h, g_w1h);
    cudaGetSymbolAddress((void**)&pw2h, g_w2h);
    cudaGetSymbolAddress((void**)&pqh,  g_qh);
    cudaGetSymbolAddress((void**)&pkh,  g_kh);
    cudaGetSymbolAddress((void**)&pvh,  g_vh);
    cudaGetSymbolAddress((void**)&pctxh,g_ctxh);
    cudaGetSymbolAddress((void**)&px1h, g_x1h);
    cudaGetSymbolAddress((void**)&pffh, g_ffh);
    cudaGetSymbolAddress((void**)&pt0,  g_t0);
    cudaGetSymbolAddress((void**)&px1,  g_x1);

    const int SMEM_G = (128*40 + 32*136) * 4 * 2;        // 4 stages
    const int SMEM_S = 2 * (128*72 + 64*72) * 2;         // 55296
    const int SMEM_C = 4 * (2*128*40 + 32*72) * 2;       // 100352
    cudaFuncSetAttribute(gemm_h<0,false>, cudaFuncAttributeMaxDynamicSharedMemorySize, SMEM_G);
    cudaFuncSetAttribute(gemm_h<1,false>, cudaFuncAttributeMaxDynamicSharedMemorySize, SMEM_G);
    cudaFuncSetAttribute(gemm_h<2,true >, cudaFuncAttributeMaxDynamicSharedMemorySize, SMEM_G);
    cudaFuncSetAttribute(scoresum_h, cudaFuncAttributeMaxDynamicSharedMemorySize, SMEM_S);
    cudaFuncSetAttribute(ctx_h,      cudaFuncAttributeMaxDynamicSharedMemorySize, SMEM_C);

    // one fused conversion kernel: 16777216 elements / 8 per thread / 256
    f2h_all<<<8192, 256>>>(x, wq, wk, wv, wo, w1, w2,
                           pxh, pwqh, pwkh, pwvh, pwoh, pw1h, pw2h);

    const dim3 gDD(CD / 128, CM / 128);

    gemm_h<1, false><<<gDD, 256, SMEM_G>>>(pxh, pwqh, bq, pqh, CM, CD, CD);
    gemm_h<1, false><<<gDD, 256, SMEM_G>>>(pxh, pwkh, bk, pkh, CM, CD, CD);
    gemm_h<1, false><<<gDD, 256, SMEM_G>>>(pxh, pwvh, bv, pvh, CM, CD, CD);

    scoresum_h<<<dim3(CS/64, CS/128, CB), 256, SMEM_S>>>();
    ctx_h<<<dim3(CS/128, CB*CH), 256, SMEM_C>>>();

    gemm_h<0, false><<<gDD, 256, SMEM_G>>>(pctxh, pwoh, bo, pt0, CM, CD, CD);
    ln_kernel<<<CM, 256>>>(x, pt0, g1, be1, px1, px1h);

    gemm_h<2, true ><<<dim3(CDFF/128, CM/128), 256, SMEM_G>>>(px1h, pw1h, b1, pffh, CM, CDFF, CD);
    gemm_h<0, false><<<gDD, 256, SMEM_G>>>(pffh, pw2h, b2, pt0, CM, CD, CDFF);
    ln_kernel<<<CM, 256>>>(px1, pt0, g2, be2, out, nullptr);
}

// round 12
// speedup vs baseline: 6.4858x; 1.0509x over previous
#include <cuda_runtime.h>
#include <cuda_fp16.h>
#include <cstdint>

constexpr int CB  = 2;
constexpr int CS  = 2048;
constexpr int CD  = 1024;
constexpr int CH  = 16;
constexpr int CDK = 64;
constexpr int CDFF= 4096;
constexpr int CM  = CB * CS;   // 4096

// ------------------------- scratch (device globals) --------------------------
__device__ __half g_xh [(size_t)CM*CD];
__device__ __half g_wqkvh[(size_t)CD*3*CD];
__device__ __half g_woh[(size_t)CD*CD];
__device__ __half g_w1h[(size_t)CD*CDFF];
__device__ __half g_w2h[(size_t)CDFF*CD];
__device__ __half g_qh [(size_t)CB*CH*CS*CDK];
__device__ __half g_kh [(size_t)CB*CH*CS*CDK];
__device__ __half g_vh [(size_t)CB*CH*CS*CDK];
__device__ __half g_Eh [(size_t)CB*CH*CS*CS];
__device__ __half g_rdh[(size_t)CB*CS*CS];
__device__ __half g_ctxh[(size_t)CM*CD];
__device__ __half g_x1h[(size_t)CM*CD];
__device__ __half g_ffh[(size_t)CM*CDFF];
__device__ float  g_t0 [(size_t)CM*CD];
__device__ float  g_x1 [(size_t)CM*CD];

// ------------------------- helpers ------------------------------------------
__device__ __forceinline__ float fast_exp(float x) {
    const float L2E = 1.4426950408889634f;
    float t = fmaf(x, L2E, 12582912.0f);
    int   e = __float_as_int(t) - 0x4B400000;
    float r = t - 12582912.0f;
    float f = fmaf(x, L2E, -r);
    float p =            1.3333558e-3f;
    p = fmaf(p, f, 9.6181291e-3f);
    p = fmaf(p, f, 5.5504109e-2f);
    p = fmaf(p, f, 2.4022651e-1f);
    p = fmaf(p, f, 6.9314718e-1f);
    p = fmaf(p, f, 1.0f);
    return __int_as_float(__float_as_int(p) + (e << 23));
}
__device__ __forceinline__ uint32_t smem_u32(const void* p) {
    uint32_t a;
    asm("{ .reg .u64 t; cvta.to.shared.u64 t, %1; cvt.u32.u64 %0, t; }" : "=r"(a) : "l"(p));
    return a;
}
__device__ __forceinline__ void cp16(uint32_t dst, const void* src) {
    asm volatile("cp.async.cg.shared.global [%0], [%1], 16;"
                 :: "r"(dst), "l"((unsigned long long)__cvta_generic_to_global(src)));
}
#define CP_COMMIT() asm volatile("cp.async.commit_group;" ::: "memory")
#define CP_WAIT(n)  asm volatile("cp.async.wait_group %0;" :: "n"(n) : "memory")

#define LDSM4(r, a) \
    asm volatile("ldmatrix.sync.aligned.m8n8.x4.shared.b16 {%0,%1,%2,%3}, [%4];" \
        : "=r"((r)[0]), "=r"((r)[1]), "=r"((r)[2]), "=r"((r)[3]) : "r"(a))
#define LDSM4T(r, a) \
    asm volatile("ldmatrix.sync.aligned.m8n8.x4.trans.shared.b16 {%0,%1,%2,%3}, [%4];" \
        : "=r"((r)[0]), "=r"((r)[1]), "=r"((r)[2]), "=r"((r)[3]) : "r"(a))
#define MMA16(c, a, b0, b1) \
    asm volatile("mma.sync.aligned.m16n8k16.row.col.f32.f16.f16.f32 " \
        "{%0,%1,%2,%3},{%4,%5,%6,%7},{%8,%9},{%0,%1,%2,%3};" \
        : "+f"((c)[0]), "+f"((c)[1]), "+f"((c)[2]), "+f"((c)[3]) \
        : "r"((a)[0]), "r"((a)[1]), "r"((a)[2]), "r"((a)[3]), "r"(b0), "r"(b1))

__device__ __forceinline__ uint32_t hmul2u(uint32_t a, uint32_t b) {
    __half2 r = __hmul2(*(__half2*)&a, *(__half2*)&b);
    return *(uint32_t*)&r;
}

// ------------------------- fused f32 -> f16 convert --------------------------
// x -> xh; wq/wk/wv -> concatenated wqkv [1024][3072]; wo/w1/w2 plain.
__global__ void f2h_all(const float* __restrict__ x,
                        const float* __restrict__ wq, const float* __restrict__ wk,
                        const float* __restrict__ wv, const float* __restrict__ wo,
                        const float* __restrict__ w1, const float* __restrict__ w2,
                        __half* __restrict__ xh, __half* __restrict__ wqkvh,
                        __half* __restrict__ woh,
                        __half* __restrict__ w1h, __half* __restrict__ w2h)
{
    const size_t e8 = ((size_t)blockIdx.x * 256 + threadIdx.x) * 8;
    const float* s; __half* d; size_t off, dst;
    if (e8 < 4194304) { s = x; d = xh; off = e8; dst = off; }
    else if (e8 < 7340032) {                       // wq/wk/wv -> wqkv
        const size_t o = e8 - 4194304;
        const int proj = (int)(o >> 20);           // 0,1,2
        off = o & 1048575;
        s = proj == 0 ? wq : (proj == 1 ? wk : wv);
        d = wqkvh;
        const size_t k = off >> 10, c = off & 1023;
        dst = k * 3072 + proj * 1024 + c;
    }
    else if (e8 <  8388608) { s = wo; d = woh; off = e8 - 7340032; dst = off; }
    else if (e8 < 12582912) { s = w1; d = w1h; off = e8 - 8388608; dst = off; }
    else                    { s = w2; d = w2h; off = e8 - 12582912; dst = off; }
    float4 u0 = *(const float4*)(s + off);
    float4 u1 = *(const float4*)(s + off + 4);
    __half2 h0 = __floats2half2_rn(u0.x, u0.y);
    __half2 h1 = __floats2half2_rn(u0.z, u0.w);
    __half2 h2 = __floats2half2_rn(u1.x, u1.y);
    __half2 h3 = __floats2half2_rn(u1.z, u1.w);
    uint4 o;
    o.x = *(uint32_t*)&h0; o.y = *(uint32_t*)&h1;
    o.z = *(uint32_t*)&h2; o.w = *(uint32_t*)&h3;
    *(uint4*)(d + dst) = o;
}

// ------------------------- shared mainloop pieces (BK=64) --------------------
// A tile [128][72] halves, B tile [64][136] halves. 3-stage ring.
constexpr int G_AST = 72, G_BST = 136;
constexpr int G_ASZ = 128 * G_AST, G_BSZ = 64 * G_BST;
constexpr int G_STG = G_ASZ + G_BSZ;                       // 17920 halves

__device__ __forceinline__ void g_issue(uint32_t smb, int tid, int kt,
                                        const __half* A, const __half* W,
                                        int K, int N, int bm, int bn)
{
    const int st = kt % 3;
    const __half* As = A + (size_t)bm * K + kt * 64;
    const __half* Ws = W + (size_t)(kt * 64) * N + bn;
    #pragma unroll
    for (int i = 0; i < 4; i++) {
        const int c = i * 256 + tid;
        const int r = c >> 3, h8 = (c & 7) * 8;
        cp16(smb + (st * G_STG + r * G_AST + h8) * 2, As + (size_t)r * K + h8);
    }
    #pragma unroll
    for (int i = 0; i < 4; i++) {
        const int c = i * 256 + tid;
        const int kk = c >> 4, n8 = (c & 15) * 8;
        cp16(smb + (st * G_STG + G_ASZ + kk * G_BST + n8) * 2, Ws + (size_t)kk * N + n8);
    }
}

__device__ __forceinline__ void g_compute(uint32_t smb, int kt, int lane,
                                          int wm, int wn, float acc[2][8][4])
{
    const uint32_t stA = smb + (kt % 3) * G_STG * 2;
    const uint32_t stB = stA + G_ASZ * 2;
    #pragma unroll
    for (int h16 = 0; h16 < 4; h16++) {
        const int kk16 = h16 * 16;
        uint32_t a[2][4], b[8][2];
        #pragma unroll
        for (int mi = 0; mi < 2; mi++) {
            const uint32_t ad = stA +
                ((wm * 32 + mi * 16 + (lane & 15)) * G_AST + kk16 + (lane >> 4) * 8) * 2;
            LDSM4(a[mi], ad);
        }
        #pragma unroll
        for (int p = 0; p < 4; p++) {
            const int n0 = wn * 64 + p * 16;
            const uint32_t ad = stB +
                ((kk16 + (lane & 7) + ((lane >> 3) & 1) * 8) * G_BST + n0 + (lane >> 4) * 8) * 2;
            uint32_t r[4];
            LDSM4T(r, ad);
            b[2*p  ][0] = r[0]; b[2*p  ][1] = r[1];
            b[2*p+1][0] = r[2]; b[2*p+1][1] = r[3];
        }
        #pragma unroll
        for (int mi = 0; mi < 2; mi++)
            #pragma unroll
            for (int ni = 0; ni < 8; ni++)
                MMA16(acc[mi][ni], a[mi], b[ni][0], b[ni][1]);
    }
}

// ======================= dense GEMM fp16 (BK=64, 3-stage) ====================
template<int OMODE, bool RELU>       // 0: fp32 rm, 2: fp16 rm
__global__ __launch_bounds__(256, 2)
void gemm_h(const __half* __restrict__ A, const __half* __restrict__ W,
            const float* __restrict__ bias, void* __restrict__ Cout,
            int M, int N, int K)
{
    extern __shared__ __half sh[];
    const uint32_t smb = smem_u32(sh);
    const int tid = threadIdx.x, wid = tid >> 5, lane = tid & 31;
    const int wm = wid >> 1, wn = wid & 1;
    const int gid = lane >> 2, tig = lane & 3;
    const int bm = blockIdx.y * 128, bn = blockIdx.x * 128;

    float acc[2][8][4] = {};
    const int nt = K / 64;
    g_issue(smb, tid, 0, A, W, K, N, bm, bn); CP_COMMIT();
    g_issue(smb, tid, 1, A, W, K, N, bm, bn); CP_COMMIT();

    for (int kt = 0; kt < nt; kt++) {
        CP_WAIT(1);
        __syncthreads();
        if (kt + 2 < nt) g_issue(smb, tid, kt + 2, A, W, K, N, bm, bn);
        CP_COMMIT();
        g_compute(smb, kt, lane, wm, wn, acc);
    }

    #pragma unroll
    for (int mi = 0; mi < 2; mi++) {
        #pragma unroll
        for (int ni = 0; ni < 8; ni++) {
            const int row = bm + wm * 32 + mi * 16 + gid;
            const int col = bn + wn * 64 + ni * 8 + tig * 2;
            const float2 b2 = *(const float2*)(bias + col);
            float v0 = acc[mi][ni][0] + b2.x, v1 = acc[mi][ni][1] + b2.y;
            float v2 = acc[mi][ni][2] + b2.x, v3 = acc[mi][ni][3] + b2.y;
            if (RELU) { v0 = fmaxf(v0, 0.f); v1 = fmaxf(v1, 0.f);
                        v2 = fmaxf(v2, 0.f); v3 = fmaxf(v3, 0.f); }
            if (OMODE == 0) {
                float* C = (float*)Cout;
                *(float2*)(C + (size_t)row       * N + col) = make_float2(v0, v1);
                *(float2*)(C + (size_t)(row + 8) * N + col) = make_float2(v2, v3);
            } else {
                __half* C = (__half*)Cout;
                *(__half2*)(C + (size_t)row       * N + col) = __floats2half2_rn(v0, v1);
                *(__half2*)(C + (size_t)(row + 8) * N + col) = __floats2half2_rn(v2, v3);
            }
        }
    }
}

// ======================= fused QKV GEMM (N=3072) =============================
__global__ __launch_bounds__(256, 2)
void gemm_qkv(const __half* __restrict__ A, const __half* __restrict__ W,
              const float* __restrict__ bq, const float* __restrict__ bk,
              const float* __restrict__ bv,
              __half* __restrict__ Oq, __half* __restrict__ Ok,
              __half* __restrict__ Ov)
{
    constexpr int K = CD, N = 3 * CD;
    extern __shared__ __half sh[];
    const uint32_t smb = smem_u32(sh);
    const int tid = threadIdx.x, wid = tid >> 5, lane = tid & 31;
    const int wm = wid >> 1, wn = wid & 1;
    const int gid = lane >> 2, tig = lane & 3;
    const int bm = blockIdx.y * 128, bn = blockIdx.x * 128;

    float acc[2][8][4] = {};
    const int nt = K / 64;
    g_issue(smb, tid, 0, A, W, K, N, bm, bn); CP_COMMIT();
    g_issue(smb, tid, 1, A, W, K, N, bm, bn); CP_COMMIT();

    for (int kt = 0; kt < nt; kt++) {
        CP_WAIT(1);
        __syncthreads();
        if (kt + 2 < nt) g_issue(smb, tid, kt + 2, A, W, K, N, bm, bn);
        CP_COMMIT();
        g_compute(smb, kt, lane, wm, wn, acc);
    }

    const int cb = bn + wn * 64;                 // multiple of 64
    const int proj = cb >> 10;
    const int h = (cb >> 6) & 15;
    __half* O = proj == 0 ? Oq : (proj == 1 ? Ok : Ov);
    const float* bs = proj == 0 ? bq : (proj == 1 ? bk : bv);
    #pragma unroll
    for (int mi = 0; mi < 2; mi++) {
        #pragma unroll
        for (int ni = 0; ni < 8; ni++) {
            const int row = bm + wm * 32 + mi * 16 + gid;
            const int dk = ni * 8 + tig * 2;
            const float2 b2 = *(const float2*)(bs + h * 64 + dk);
            const int b = row >> 11, s1 = row & (CS - 1);
            const size_t base = (((size_t)(b * CH + h)) * CS + s1) * CDK + dk;
            *(__half2*)(O + base) =
                __floats2half2_rn(acc[mi][ni][0] + b2.x, acc[mi][ni][1] + b2.y);
            *(__half2*)(O + base + (size_t)8 * CDK) =
                __floats2half2_rn(acc[mi][ni][2] + b2.x, acc[mi][ni][3] + b2.y);
        }
    }
}

// ======================= scores + denom fused ================================
__global__ __launch_bounds__(256, 2)
void scoresum_h()
{
    constexpr int QST = 72;
    constexpr int QSZ = 128 * QST, KSZ = 64 * QST, STG = QSZ + KSZ;
    extern __shared__ __half sh[];
    const uint32_t smb = smem_u32(sh);

    const int tid = threadIdx.x, wid = tid >> 5, lane = tid & 31;
    const int wm = wid >> 1, wn = wid & 1;
    const int gid = lane >> 2, tig = lane & 3;
    const int b = blockIdx.z;
    const int q0 = blockIdx.y * 128, k0 = blockIdx.x * 64;
    const size_t plane = (size_t)CS * CS;

    auto issue = [&](int h) {
        const int st = h & 1;
        const __half* qb = g_qh + ((size_t)(b * CH + h)) * CS * CDK + (size_t)q0 * CDK;
        const __half* kb = g_kh + ((size_t)(b * CH + h)) * CS * CDK + (size_t)k0 * CDK;
        #pragma unroll
        for (int i = 0; i < 4; i++) {
            const int c = i * 256 + tid;
            const int r = c >> 3, h8 = (c & 7) * 8;
            cp16(smb + (st * STG + r * QST + h8) * 2, qb + (size_t)r * CDK + h8);
        }
        #pragma unroll
        for (int i = 0; i < 2; i++) {
            const int c = i * 256 + tid;
            const int r = c >> 3, h8 = (c & 7) * 8;
            cp16(smb + (st * STG + QSZ + r * QST + h8) * 2, kb + (size_t)r * CDK + h8);
        }
    };

    float sum[2][4][4] = {};
    issue(0); CP_COMMIT();

    for (int h = 0; h < CH; h++) {
        if (h + 1 < CH) { issue(h + 1); CP_COMMIT(); CP_WAIT(1); }
        else            { CP_WAIT(0); }
        __syncthreads();

        const uint32_t stQ = smb + (h & 1) * STG * 2;
        const uint32_t stK = stQ + QSZ * 2;

        float acc[2][4][4] = {};
        #pragma unroll
        for (int h16 = 0; h16 < 4; h16++) {
            const int kk16 = h16 * 16;
            uint32_t a[2][4], bfr[4][2];
            #pragma unroll
            for (int mi = 0; mi < 2; mi++) {
                const uint32_t ad = stQ +
                    ((wm * 32 + mi * 16 + (lane & 15)) * QST + kk16 + (lane >> 4) * 8) * 2;
                LDSM4(a[mi], ad);
            }
            #pragma unroll
            for (int p = 0; p < 2; p++) {
                const int n0 = wn * 32 + p * 16;
                const uint32_t ad = stK +
                    ((n0 + (lane & 15)) * QST + kk16 + (lane >> 4) * 8) * 2;
                uint32_t r[4];
                LDSM4(r, ad);
                bfr[2*p  ][0] = r[0]; bfr[2*p  ][1] = r[2];
                bfr[2*p+1][0] = r[1]; bfr[2*p+1][1] = r[3];
            }
            #pragma unroll
            for (int mi = 0; mi < 2; mi++)
                #pragma unroll
                for (int ni = 0; ni < 4; ni++)
                    MMA16(acc[mi][ni], a[mi], bfr[ni][0], bfr[ni][1]);
        }

        __half* Eb = g_Eh + ((size_t)(b * CH + h)) * plane;
        #pragma unroll
        for (int mi = 0; mi < 2; mi++) {
            #pragma unroll
            for (int ni = 0; ni < 4; ni++) {
                const int q = q0 + wm * 32 + mi * 16 + gid;
                const int k = k0 + wn * 32 + ni * 8 + tig * 2;
                float e0 = fast_exp(acc[mi][ni][0] * 0.125f);
                float e1 = fast_exp(acc[mi][ni][1] * 0.125f);
                float e2 = fast_exp(acc[mi][ni][2] * 0.125f);
                float e3 = fast_exp(acc[mi][ni][3] * 0.125f);
                sum[mi][ni][0] += e0; sum[mi][ni][1] += e1;
                sum[mi][ni][2] += e2; sum[mi][ni][3] += e3;
                *(__half2*)(Eb + (size_t)q       * CS + k) = __floats2half2_rn(e0, e1);
                *(__half2*)(Eb + (size_t)(q + 8) * CS + k) = __floats2half2_rn(e2, e3);
            }
        }
        __syncthreads();
    }

    __half* rdb = g_rdh + (size_t)b * plane;
    #pragma unroll
    for (int mi = 0; mi < 2; mi++) {
        #pragma unroll
        for (int ni = 0; ni < 4; ni++) {
            const int q = q0 + wm * 32 + mi * 16 + gid;
            const int k = k0 + wn * 32 + ni * 8 + tig * 2;
            *(__half2*)(rdb + (size_t)q       * CS + k) =
                __floats2half2_rn(1.0f / sum[mi][ni][0], 1.0f / sum[mi][ni][1]);
            *(__half2*)(rdb + (size_t)(q + 8) * CS + k) =
                __floats2half2_rn(1.0f / sum[mi][ni][2], 1.0f / sum[mi][ni][3]);
        }
    }
}

// ======================= ctx: (E*rd) @ V, BK=64, 2-stage =====================
__global__ __launch_bounds__(256, 2)
void ctx_h()
{
    constexpr int EST = 72, VST = 72;
    constexpr int ESZ = 128 * EST, VSZ = 64 * VST;
    constexpr int STG = 2 * ESZ + VSZ;                      // 23040 halves
    extern __shared__ __half sh[];
    const uint32_t smb = smem_u32(sh);

    const int tid = threadIdx.x, wid = tid >> 5, lane = tid & 31;
    const int wm = wid >> 1, wn = wid & 1;
    const int gid = lane >> 2, tig = lane & 3;
    const int bh = blockIdx.y;
    const int b = bh >> 4, h = bh & 15;
    const int q0 = blockIdx.x * 128;
    const size_t plane = (size_t)CS * CS;
    const __half* eb = g_Eh  + (size_t)bh * plane;
    const __half* rb = g_rdh + (size_t)b  * plane;
    const __half* vb = g_vh  + (size_t)bh * CS * CDK;

    auto issue = [&](int kt) {
        const int st = kt & 1;
        const int kb = kt * 64;
        #pragma unroll
        for (int i = 0; i < 4; i++) {
            const int c = i * 256 + tid;
            const int r = c >> 3, h8 = (c & 7) * 8;
            cp16(smb + (st * STG + r * EST + h8) * 2,       eb + (size_t)(q0 + r) * CS + kb + h8);
            cp16(smb + (st * STG + ESZ + r * EST + h8) * 2, rb + (size_t)(q0 + r) * CS + kb + h8);
        }
        #pragma unroll
        for (int i = 0; i < 2; i++) {
            const int c = i * 256 + tid;
            const int kk = c >> 3, n8 = (c & 7) * 8;
            cp16(smb + (st * STG + 2 * ESZ + kk * VST + n8) * 2, vb + (size_t)(kb + kk) * CDK + n8);
        }
    };

    float acc[2][4][4] = {};
    const int nt = CS / 64;
    issue(0); CP_COMMIT();

    for (int kt = 0; kt < nt; kt++) {
        CP_WAIT(0);
        __syncthreads();
        if (kt + 1 < nt) issue(kt + 1);
        CP_COMMIT();

        const uint32_t stE = smb + (kt & 1) * STG * 2;
        const uint32_t stR = stE + ESZ * 2;
        const uint32_t stV = stR + ESZ * 2;
        #pragma unroll
        for (int h16 = 0; h16 < 4; h16++) {
            const int kk16 = h16 * 16;
            uint32_t ae[2][4], ar[2][4], a[2][4], bv[4][2];
            #pragma unroll
            for (int mi = 0; mi < 2; mi++) {
                const uint32_t off =
                    ((wm * 32 + mi * 16 + (lane & 15)) * EST + kk16 + (lane >> 4) * 8) * 2;
                LDSM4(ae[mi], stE + off);
                LDSM4(ar[mi], stR + off);
                #pragma unroll
                for (int j = 0; j < 4; j++) a[mi][j] = hmul2u(ae[mi][j], ar[mi][j]);
            }
            #pragma unroll
            for (int p = 0; p < 2; p++) {
                const int n0 = wn * 32 + p * 16;
                const uint32_t ad = stV +
                    ((kk16 + (lane & 7) + ((lane >> 3) & 1) * 8) * VST + n0 + (lane >> 4) * 8) * 2;
                uint32_t r[4];
                LDSM4T(r, ad);
                bv[2*p  ][0] = r[0]; bv[2*p  ][1] = r[1];
                bv[2*p+1][0] = r[2]; bv[2*p+1][1] = r[3];
            }
            #pragma unroll
            for (int mi = 0; mi < 2; mi++)
                #pragma unroll
                for (int ni = 0; ni < 4; ni++)
                    MMA16(acc[mi][ni], a[mi], bv[ni][0], bv[ni][1]);
        }
    }

    #pragma unroll
    for (int mi = 0; mi < 2; mi++) {
        #pragma unroll
        for (int ni = 0; ni < 4; ni++) {
            const int q = q0 + wm * 32 + mi * 16 + gid;
            const int n = wn * 32 + ni * 8 + tig * 2;
            __half* p0p = g_ctxh + (((size_t)(b * CS + q    )) * CH + h) * CDK + n;
            __half* p1p = g_ctxh + (((size_t)(b * CS + q + 8)) * CH + h) * CDK + n;
            *(__half2*)p0p = __floats2half2_rn(acc[mi][ni][0], acc[mi][ni][1]);
            *(__half2*)p1p = __floats2half2_rn(acc[mi][ni][2], acc[mi][ni][3]);
        }
    }
}

// ------------------------- residual + LayerNorm ------------------------------
__global__ void ln_kernel(const float* __restrict__ A, const float* __restrict__ Bp,
                          const float* __restrict__ g, const float* __restrict__ be,
                          float* __restrict__ out, __half* __restrict__ outh)
{
    const int row = blockIdx.x;
    const int tid = threadIdx.x;
    const int i0 = tid << 2;
    float4 a  = *(const float4*)(A  + (size_t)row*CD + i0);
    float4 bb = *(const float4*)(Bp + (size_t)row*CD + i0);
    const float v0 = a.x + bb.x, v1 = a.y + bb.y, v2 = a.z + bb.z, v3 = a.w + bb.w;
    float s  = v0 + v1 + v2 + v3;
    float ss = v0*v0 + v1*v1 + v2*v2 + v3*v3;
    #pragma unroll
    for (int o = 16; o; o >>= 1) {
        s  += __shfl_xor_sync(0xffffffffu, s,  o);
        ss += __shfl_xor_sync(0xffffffffu, ss, o);
    }
    __shared__ float sh1[8], sh2[8];
    if ((tid & 31) == 0) { sh1[tid >> 5] = s; sh2[tid >> 5] = ss; }
    __syncthreads();
    s = 0.f; ss = 0.f;
    #pragma unroll
    for (int w = 0; w < 8; w++) { s += sh1[w]; ss += sh2[w]; }
    const float mean = s * (1.0f / CD);
    const float var  = ss * (1.0f / CD) - mean * mean;
    const float rstd = rsqrtf(var + 1e-5f);
    float4 gg = *(const float4*)(g  + i0);
    float4 bt = *(const float4*)(be + i0);
    float4 o4;
    o4.x = (v0 - mean) * rstd * gg.x + bt.x;
    o4.y = (v1 - mean) * rstd * gg.y + bt.y;
    o4.z = (v2 - mean) * rstd * gg.z + bt.z;
    o4.w = (v3 - mean) * rstd * gg.w + bt.w;
    *(float4*)(out + (size_t)row*CD + i0) = o4;
    if (outh) {
        __half2 h0 = __floats2half2_rn(o4.x, o4.y);
        __half2 h1 = __floats2half2_rn(o4.z, o4.w);
        uint2 u; u.x = *(uint32_t*)&h0; u.y = *(uint32_t*)&h1;
        *(uint2*)(outh + (size_t)row*CD + i0) = u;
    }
}

// ------------------------- launch -------------------------------------------
extern "C" void kernel_launch(void* const* d_in, const int* in_sizes, int n_in,
                              void* d_out, int out_size)
{
    (void)in_sizes; (void)n_in; (void)out_size;
    const float* x   = (const float*)d_in[0];
    const float* wq  = (const float*)d_in[1];
    const float* bq  = (const float*)d_in[2];
    const float* wk  = (const float*)d_in[3];
    const float* bk  = (const float*)d_in[4];
    const float* wv  = (const float*)d_in[5];
    const float* bv  = (const float*)d_in[6];
    const float* wo  = (const float*)d_in[7];
    const float* bo  = (const float*)d_in[8];
    const float* g1  = (const float*)d_in[9];
    const float* be1 = (const float*)d_in[10];
    const float* w1  = (const float*)d_in[11];
    const float* b1  = (const float*)d_in[12];
    const float* w2  = (const float*)d_in[13];
    const float* b2  = (const float*)d_in[14];
    const float* g2  = (const float*)d_in[15];
    const float* be2 = (const float*)d_in[16];
    float* out = (float*)d_out;

    __half *pxh, *pwqkvh, *pwoh, *pw1h, *pw2h;
    __half *pqh, *pkh, *pvh, *pctxh, *px1h, *pffh;
    float *pt0, *px1;
    cudaGetSymbolAddress((void**)&pxh,    g_xh);
    cudaGetSymbolAddress((void**)&pwqkvh, g_wqkvh);
    cudaGetSymbolAddress((void**)&pwoh,   g_woh);
    cudaGetSymbolAddress((void**)&pw1h,   g_w1h);
    cudaGetSymbolAddress((void**)&pw2h,   g_w2h);
    cudaGetSymbolAddress((void**)&pqh,    g_qh);
    cudaGetSymbolAddress((void**)&pkh,    g_kh);
    cudaGetSymbolAddress((void**)&pvh,    g_vh);
    cudaGetSymbolAddress((void**)&pctxh,  g_ctxh);
    cudaGetSymbolAddress((void**)&px1h,   g_x1h);
    cudaGetSymbolAddress((void**)&pffh,   g_ffh);
    cudaGetSymbolAddress((void**)&pt0,    g_t0);
    cudaGetSymbolAddress((void**)&px1,    g_x1);

    const int SMEM_G = 3 * G_STG * 2;                    // 107520
    const int SMEM_S = 2 * (192 * 72) * 2;               // 55296
    const int SMEM_C = 2 * (2 * 128 * 72 + 64 * 72) * 2; // 92160
    cudaFuncSetAttribute(gemm_h<0,false>, cudaFuncAttributeMaxDynamicSharedMemorySize, SMEM_G);
    cudaFuncSetAttribute(gemm_h<2,true >, cudaFuncAttributeMaxDynamicSharedMemorySize, SMEM_G);
    cudaFuncSetAttribute(gemm_qkv,  cudaFuncAttributeMaxDynamicSharedMemorySize, SMEM_G);
    cudaFuncSetAttribute(scoresum_h, cudaFuncAttributeMaxDynamicSharedMemorySize, SMEM_S);
    cudaFuncSetAttribute(ctx_h,      cudaFuncAttributeMaxDynamicSharedMemorySize, SMEM_C);

    f2h_all<<<8192, 256>>>(x, wq, wk, wv, wo, w1, w2,
                           pxh, pwqkvh, pwoh, pw1h, pw2h);

    gemm_qkv<<<dim3(3*CD/128, CM/128), 256, SMEM_G>>>(pxh, pwqkvh, bq, bk, bv,
                                                      pqh, pkh, pvh);

    scoresum_h<<<dim3(CS/64, CS/128, CB), 256, SMEM_S>>>();
    ctx_h<<<dim3(CS/128, CB*CH), 256, SMEM_C>>>();

    const dim3 gDD(CD / 128, CM / 128);
    gemm_h<0, false><<<gDD, 256, SMEM_G>>>(pctxh, pwoh, bo, pt0, CM, CD, CD);
    ln_kernel<<<CM, 256>>>(x, pt0, g1, be1, px1, px1h);

    gemm_h<2, true ><<<dim3(CDFF/128, CM/128), 256, SMEM_G>>>(px1h, pw1h, b1, pffh, CM, CDFF, CD);
    gemm_h<0, false><<<gDD, 256, SMEM_G>>>(pffh, pw2h, b2, pt0, CM, CD, CDFF);
    ln_kernel<<<CM, 256>>>(px1, pt0, g2, be2, out, nullptr);
}